// round 1
// baseline (speedup 1.0000x reference)
#include <cuda_runtime.h>
#include <math.h>

#define BB 2
#define SEQ 2048
#define DIM 1024
#define NH 16
#define DH 64

constexpr int BS = BB * SEQ;                       // 4096 rows
constexpr size_t QKV_ELEMS = (size_t)BB * NH * SEQ * DH;  // 4,194,304
constexpr size_t CTX_ELEMS = (size_t)BS * DIM;            // 4,194,304

__device__ float g_q[QKV_ELEMS];
__device__ float g_k[QKV_ELEMS];
__device__ float g_v[QKV_ELEMS];
__device__ float g_ctx[CTX_ELEMS];

// ---------------------------------------------------------------------------
// Generic 64x64-tile fp32 GEMM: C = A[M,K] @ W[K,N] + bias[N]
// HEADSPLIT=true  -> C written in [B,H,S,DH] layout (for Q/K/V projections)
// HEADSPLIT=false -> C written plain row-major [M,N]
// 256 threads (16x16), 4x4 accumulators per thread, BK=16.
// ---------------------------------------------------------------------------
template <bool HEADSPLIT>
__global__ void gemm_kernel(const float* __restrict__ A,
                            const float* __restrict__ W,
                            const float* __restrict__ bias,
                            float* __restrict__ C,
                            int M, int N, int K) {
    __shared__ float As[16][65];   // As[kk][m]
    __shared__ float Bs[16][65];   // Bs[kk][n]

    const int bm = blockIdx.y * 64;
    const int bn = blockIdx.x * 64;
    const int tid = threadIdx.x;
    const int tx = tid % 16;
    const int ty = tid / 16;

    float acc[4][4] = {};

    for (int k0 = 0; k0 < K; k0 += 16) {
#pragma unroll
        for (int l = 0; l < 4; l++) {
            int idx = tid + l * 256;            // 0..1023
            int m  = idx >> 4, kk  = idx & 15;  // A tile: 64 x 16
            As[kk][m] = A[(size_t)(bm + m) * K + k0 + kk];
            int kk2 = idx >> 6, n = idx & 63;   // W tile: 16 x 64
            Bs[kk2][n] = W[(size_t)(k0 + kk2) * N + bn + n];
        }
        __syncthreads();
#pragma unroll
        for (int kk = 0; kk < 16; kk++) {
            float a[4], b[4];
#pragma unroll
            for (int i = 0; i < 4; i++) a[i] = As[kk][ty * 4 + i];
#pragma unroll
            for (int j = 0; j < 4; j++) b[j] = Bs[kk][tx * 4 + j];
#pragma unroll
            for (int i = 0; i < 4; i++)
#pragma unroll
                for (int j = 0; j < 4; j++) acc[i][j] += a[i] * b[j];
        }
        __syncthreads();
    }

#pragma unroll
    for (int i = 0; i < 4; i++) {
#pragma unroll
        for (int j = 0; j < 4; j++) {
            int m = bm + ty * 4 + i;
            int n = bn + tx * 4 + j;
            float v = acc[i][j] + bias[n];
            if (HEADSPLIT) {
                int b  = m >> 11;       // m / SEQ
                int s  = m & 2047;      // m % SEQ
                int h  = n >> 6;        // n / DH
                int dh = n & 63;        // n % DH
                C[(((size_t)b * NH + h) * SEQ + s) * DH + dh] = v;
            } else {
                C[(size_t)m * N + n] = v;
            }
        }
    }
}

// ---------------------------------------------------------------------------
// Logits: attn[bh, qi, kj] = scale * sum_d Q[bh,qi,d]*K[bh,kj,d] + mask*(-1e9)
// Grid: (ktile=32, qtile=32, bh=32). 64x64 output tile, full K-dim = 64.
// ---------------------------------------------------------------------------
__global__ void logits_kernel(const float* __restrict__ mask,
                              float* __restrict__ attn) {
    const int bh = blockIdx.z;
    const int qt = blockIdx.y * 64;
    const int kt = blockIdx.x * 64;
    const float* Q  = g_q + (size_t)bh * SEQ * DH;
    const float* Kp = g_k + (size_t)bh * SEQ * DH;

    __shared__ float Qs[64][65];
    __shared__ float Ks[64][65];

    const int tid = threadIdx.x;
#pragma unroll
    for (int l = 0; l < 16; l++) {
        int idx = tid + l * 256;       // 0..4095
        int r = idx >> 6, c = idx & 63;
        Qs[r][c] = Q[(size_t)(qt + r) * DH + c];
        Ks[r][c] = Kp[(size_t)(kt + r) * DH + c];
    }
    __syncthreads();

    const int tx = tid % 16;
    const int ty = tid / 16;
    float acc[4][4] = {};
#pragma unroll
    for (int d = 0; d < 64; d++) {
        float a[4], b[4];
#pragma unroll
        for (int i = 0; i < 4; i++) a[i] = Qs[ty * 4 + i][d];
#pragma unroll
        for (int j = 0; j < 4; j++) b[j] = Ks[tx * 4 + j][d];
#pragma unroll
        for (int i = 0; i < 4; i++)
#pragma unroll
            for (int j = 0; j < 4; j++) acc[i][j] += a[i] * b[j];
    }

    const float scale = 0.125f;   // 1/sqrt(64)
#pragma unroll
    for (int i = 0; i < 4; i++) {
#pragma unroll
        for (int j = 0; j < 4; j++) {
            int qi = qt + ty * 4 + i;
            int kj = kt + tx * 4 + j;
            float v = acc[i][j] * scale + mask[(size_t)qi * SEQ + kj] * (-1e9f);
            attn[((size_t)bh * SEQ + qi) * SEQ + kj] = v;
        }
    }
}

// ---------------------------------------------------------------------------
// Row softmax, in place. One block (256 thr) per row of 2048.
// ---------------------------------------------------------------------------
__global__ void softmax_kernel(float* __restrict__ attn) {
    const int tid = threadIdx.x;
    float* p = attn + (size_t)blockIdx.x * SEQ;

    float v[8];
    float mx = -1e30f;
#pragma unroll
    for (int l = 0; l < 8; l++) {
        v[l] = p[tid + l * 256];
        mx = fmaxf(mx, v[l]);
    }
    __shared__ float smax[8];
    __shared__ float ssum[8];
#pragma unroll
    for (int o = 16; o > 0; o >>= 1) mx = fmaxf(mx, __shfl_xor_sync(0xffffffffu, mx, o));
    if ((tid & 31) == 0) smax[tid >> 5] = mx;
    __syncthreads();
    float bmx = fmaxf(fmaxf(fmaxf(smax[0], smax[1]), fmaxf(smax[2], smax[3])),
                      fmaxf(fmaxf(smax[4], smax[5]), fmaxf(smax[6], smax[7])));

    float sum = 0.f;
#pragma unroll
    for (int l = 0; l < 8; l++) {
        v[l] = __expf(v[l] - bmx);
        sum += v[l];
    }
#pragma unroll
    for (int o = 16; o > 0; o >>= 1) sum += __shfl_xor_sync(0xffffffffu, sum, o);
    if ((tid & 31) == 0) ssum[tid >> 5] = sum;
    __syncthreads();
    float tot = (ssum[0] + ssum[1]) + (ssum[2] + ssum[3]) +
                (ssum[4] + ssum[5]) + (ssum[6] + ssum[7]);
    float inv = 1.0f / tot;
#pragma unroll
    for (int l = 0; l < 8; l++) p[tid + l * 256] = v[l] * inv;
}

// ---------------------------------------------------------------------------
// ctx = attn @ V, written directly in merged [B, S, D] layout.
// Grid: (mtile=32, bh=32). Tile 64(M) x 64(N=DH), BK=32.
// ---------------------------------------------------------------------------
__global__ void ctx_kernel(const float* __restrict__ attn) {
    const int bh = blockIdx.y;
    const int b = bh >> 4;
    const int h = bh & 15;
    const int mt = blockIdx.x * 64;
    const float* A = attn + (size_t)bh * SEQ * SEQ;
    const float* V = g_v + (size_t)bh * SEQ * DH;

    __shared__ float As[64][33];   // As[m][kk]
    __shared__ float Vs[32][65];   // Vs[kk][n]

    const int tid = threadIdx.x;
    const int tx = tid % 16;
    const int ty = tid / 16;
    float acc[4][4] = {};

    for (int k0 = 0; k0 < SEQ; k0 += 32) {
#pragma unroll
        for (int l = 0; l < 8; l++) {
            int idx = tid + l * 256;        // 0..2047
            int m = idx >> 5, kk = idx & 31;
            As[m][kk] = A[(size_t)(mt + m) * SEQ + k0 + kk];
            int kk2 = idx >> 6, n = idx & 63;
            Vs[kk2][n] = V[(size_t)(k0 + kk2) * DH + n];
        }
        __syncthreads();
#pragma unroll
        for (int kk = 0; kk < 32; kk++) {
            float a[4], bv[4];
#pragma unroll
            for (int i = 0; i < 4; i++) a[i] = As[ty * 4 + i][kk];
#pragma unroll
            for (int j = 0; j < 4; j++) bv[j] = Vs[kk][tx * 4 + j];
#pragma unroll
            for (int i = 0; i < 4; i++)
#pragma unroll
                for (int j = 0; j < 4; j++) acc[i][j] += a[i] * bv[j];
        }
        __syncthreads();
    }

#pragma unroll
    for (int i = 0; i < 4; i++) {
#pragma unroll
        for (int j = 0; j < 4; j++) {
            int s = mt + ty * 4 + i;
            int n = tx * 4 + j;
            g_ctx[((size_t)b * SEQ + s) * DIM + h * DH + n] = acc[i][j];
        }
    }
}

// ---------------------------------------------------------------------------
extern "C" void kernel_launch(void* const* d_in, const int* in_sizes, int n_in,
                              void* d_out, int out_size) {
    const float* x    = (const float*)d_in[0];
    const float* mask = (const float*)d_in[1];
    const float* Wq   = (const float*)d_in[2];
    const float* bq   = (const float*)d_in[3];
    const float* Wk   = (const float*)d_in[4];
    const float* bk   = (const float*)d_in[5];
    const float* Wv   = (const float*)d_in[6];
    const float* bv   = (const float*)d_in[7];
    const float* Wo   = (const float*)d_in[8];
    const float* bo   = (const float*)d_in[9];

    float* out  = (float*)d_out;                       // [B,S,D]
    float* attn = out + (size_t)BS * DIM;              // [B,H,S,S]

    float *qp, *kp, *vp, *cp;
    cudaGetSymbolAddress((void**)&qp, g_q);
    cudaGetSymbolAddress((void**)&kp, g_k);
    cudaGetSymbolAddress((void**)&vp, g_v);
    cudaGetSymbolAddress((void**)&cp, g_ctx);

    dim3 projGrid(DIM / 64, BS / 64);   // (16, 64)
    gemm_kernel<true><<<projGrid, 256>>>(x, Wq, bq, qp, BS, DIM, DIM);
    gemm_kernel<true><<<projGrid, 256>>>(x, Wk, bk, kp, BS, DIM, DIM);
    gemm_kernel<true><<<projGrid, 256>>>(x, Wv, bv, vp, BS, DIM, DIM);

    dim3 logitsGrid(SEQ / 64, SEQ / 64, BB * NH);  // (32, 32, 32)
    logits_kernel<<<logitsGrid, 256>>>(mask, attn);

    softmax_kernel<<<BB * NH * SEQ, 256>>>(attn);

    dim3 ctxGrid(SEQ / 64, BB * NH);   // (32, 32)
    ctx_kernel<<<ctxGrid, 256>>>(attn);

    gemm_kernel<false><<<projGrid, 256>>>(cp, Wo, bo, out, BS, DIM, DIM);
}

// round 2
// speedup vs baseline: 2.2102x; 2.2102x over previous
#include <cuda_runtime.h>
#include <math.h>

#define BB 2
#define SEQ 2048
#define DIM 1024
#define NH 16
#define DH 64

constexpr int BS = BB * SEQ;                              // 4096 rows
constexpr size_t QKV_ELEMS = (size_t)BB * NH * SEQ * DH;  // 4,194,304
constexpr size_t CTX_ELEMS = (size_t)BS * DIM;            // 4,194,304

__device__ float g_q[QKV_ELEMS];
__device__ float g_k[QKV_ELEMS];
__device__ float g_v[QKV_ELEMS];
__device__ float g_ctx[CTX_ELEMS];

// ---------------------------------------------------------------------------
// 128x128-tile fp32 GEMM: C = A[M,K] @ W[K,N] + bias[N]
// 256 threads, 8x8 accumulators per thread (split fragments), BK=16,
// register-stage prefetch double buffering, LDS.128 fragment loads.
// HEADSPLIT=true -> C written in [B,H,S,DH] layout.
// ---------------------------------------------------------------------------
template <bool HEADSPLIT>
__global__ void __launch_bounds__(256, 2)
gemm128(const float* __restrict__ A, const float* __restrict__ W,
        const float* __restrict__ bias, float* __restrict__ C,
        int M, int N, int K) {
    __shared__ float As[16][132];   // [k][m] transposed
    __shared__ float Bs[16][132];   // [k][n] natural

    const int bm = blockIdx.y * 128;
    const int bn = blockIdx.x * 128;
    const int tid = threadIdx.x;
    const int tx = tid & 15;        // n-group
    const int ty = tid >> 4;        // m-group

    float acc[8][8] = {};
    float4 ra[2], rb[2];

    // ---- load tile k0=0 ----
#pragma unroll
    for (int l = 0; l < 2; l++) {
        int slot = tid + l * 256;               // 0..511
        int row = slot >> 2, c4 = slot & 3;     // A: 128 rows x 4 float4
        ra[l] = *(const float4*)&A[(size_t)(bm + row) * K + c4 * 4];
        int kk = slot >> 5, n4 = slot & 31;     // B: 16 rows x 32 float4
        rb[l] = *(const float4*)&W[(size_t)kk * N + bn + n4 * 4];
    }
#pragma unroll
    for (int l = 0; l < 2; l++) {
        int slot = tid + l * 256;
        int row = slot >> 2, c4 = slot & 3;
        As[c4 * 4 + 0][row] = ra[l].x; As[c4 * 4 + 1][row] = ra[l].y;
        As[c4 * 4 + 2][row] = ra[l].z; As[c4 * 4 + 3][row] = ra[l].w;
        int kk = slot >> 5, n4 = slot & 31;
        *(float4*)&Bs[kk][n4 * 4] = rb[l];
    }
    __syncthreads();

    for (int k0 = 0; k0 < K; k0 += 16) {
        const bool more = (k0 + 16 < K);
        if (more) {
#pragma unroll
            for (int l = 0; l < 2; l++) {
                int slot = tid + l * 256;
                int row = slot >> 2, c4 = slot & 3;
                ra[l] = *(const float4*)&A[(size_t)(bm + row) * K + k0 + 16 + c4 * 4];
                int kk = slot >> 5, n4 = slot & 31;
                rb[l] = *(const float4*)&W[(size_t)(k0 + 16 + kk) * N + bn + n4 * 4];
            }
        }
#pragma unroll
        for (int kk = 0; kk < 16; kk++) {
            float a[8], b[8];
            *(float4*)&a[0] = *(const float4*)&As[kk][ty * 4];
            *(float4*)&a[4] = *(const float4*)&As[kk][64 + ty * 4];
            *(float4*)&b[0] = *(const float4*)&Bs[kk][tx * 4];
            *(float4*)&b[4] = *(const float4*)&Bs[kk][64 + tx * 4];
#pragma unroll
            for (int i = 0; i < 8; i++)
#pragma unroll
                for (int j = 0; j < 8; j++) acc[i][j] += a[i] * b[j];
        }
        if (more) {
            __syncthreads();
#pragma unroll
            for (int l = 0; l < 2; l++) {
                int slot = tid + l * 256;
                int row = slot >> 2, c4 = slot & 3;
                As[c4 * 4 + 0][row] = ra[l].x; As[c4 * 4 + 1][row] = ra[l].y;
                As[c4 * 4 + 2][row] = ra[l].z; As[c4 * 4 + 3][row] = ra[l].w;
                int kk = slot >> 5, n4 = slot & 31;
                *(float4*)&Bs[kk][n4 * 4] = rb[l];
            }
            __syncthreads();
        }
    }

    // ---- epilogue ----
#pragma unroll
    for (int i = 0; i < 8; i++) {
        int m = bm + ((i < 4) ? (ty * 4 + i) : (64 + ty * 4 + i - 4));
#pragma unroll
        for (int jh = 0; jh < 2; jh++) {
            int n0 = bn + (jh ? (64 + tx * 4) : (tx * 4));
            float4 v;
            v.x = acc[i][jh * 4 + 0] + bias[n0 + 0];
            v.y = acc[i][jh * 4 + 1] + bias[n0 + 1];
            v.z = acc[i][jh * 4 + 2] + bias[n0 + 2];
            v.w = acc[i][jh * 4 + 3] + bias[n0 + 3];
            if (HEADSPLIT) {
                int b = m >> 11, s = m & 2047;
                int h = n0 >> 6, dh = n0 & 63;   // 4 cols stay in one head
                *(float4*)&C[(((size_t)b * NH + h) * SEQ + s) * DH + dh] = v;
            } else {
                *(float4*)&C[(size_t)m * N + n0] = v;
            }
        }
    }
}

// ---------------------------------------------------------------------------
// Logits: 128x128 output tile per block, K=64 in one shot (no k-loop).
// attn[bh,qi,kj] = 0.125 * Q.Kt + mask*(-1e9)
// ---------------------------------------------------------------------------
__global__ void __launch_bounds__(256, 2)
logits128(const float* __restrict__ mask, float* __restrict__ attn) {
    __shared__ float Qs[64][132];   // [d][m]
    __shared__ float Ks[64][132];   // [d][n]

    const int bh = blockIdx.z;
    const int qt = blockIdx.y * 128;
    const int kt = blockIdx.x * 128;
    const float* Q  = g_q + (size_t)bh * SEQ * DH;
    const float* Kp = g_k + (size_t)bh * SEQ * DH;

    const int tid = threadIdx.x;
    const int tx = tid & 15, ty = tid >> 4;

#pragma unroll
    for (int l = 0; l < 8; l++) {
        int slot = tid + l * 256;               // 0..2047
        int row = slot >> 4, c4 = slot & 15;    // 128 rows x 16 float4
        float4 q4 = *(const float4*)&Q[(size_t)(qt + row) * DH + c4 * 4];
        Qs[c4 * 4 + 0][row] = q4.x; Qs[c4 * 4 + 1][row] = q4.y;
        Qs[c4 * 4 + 2][row] = q4.z; Qs[c4 * 4 + 3][row] = q4.w;
        float4 k4 = *(const float4*)&Kp[(size_t)(kt + row) * DH + c4 * 4];
        Ks[c4 * 4 + 0][row] = k4.x; Ks[c4 * 4 + 1][row] = k4.y;
        Ks[c4 * 4 + 2][row] = k4.z; Ks[c4 * 4 + 3][row] = k4.w;
    }
    __syncthreads();

    float acc[8][8] = {};
#pragma unroll
    for (int d = 0; d < 64; d++) {
        float a[8], b[8];
        *(float4*)&a[0] = *(const float4*)&Qs[d][ty * 4];
        *(float4*)&a[4] = *(const float4*)&Qs[d][64 + ty * 4];
        *(float4*)&b[0] = *(const float4*)&Ks[d][tx * 4];
        *(float4*)&b[4] = *(const float4*)&Ks[d][64 + tx * 4];
#pragma unroll
        for (int i = 0; i < 8; i++)
#pragma unroll
            for (int j = 0; j < 8; j++) acc[i][j] += a[i] * b[j];
    }

    const float scale = 0.125f;
#pragma unroll
    for (int i = 0; i < 8; i++) {
        int qi = qt + ((i < 4) ? (ty * 4 + i) : (64 + ty * 4 + i - 4));
#pragma unroll
        for (int jh = 0; jh < 2; jh++) {
            int kj = kt + (jh ? (64 + tx * 4) : (tx * 4));
            float4 mk = *(const float4*)&mask[(size_t)qi * SEQ + kj];
            float4 v;
            v.x = acc[i][jh * 4 + 0] * scale + mk.x * (-1e9f);
            v.y = acc[i][jh * 4 + 1] * scale + mk.y * (-1e9f);
            v.z = acc[i][jh * 4 + 2] * scale + mk.z * (-1e9f);
            v.w = acc[i][jh * 4 + 3] * scale + mk.w * (-1e9f);
            *(float4*)&attn[((size_t)bh * SEQ + qi) * SEQ + kj] = v;
        }
    }
}

// ---------------------------------------------------------------------------
// Row softmax, in place, float4 vectorized. One block (256 thr) per row.
// ---------------------------------------------------------------------------
__global__ void softmax_kernel(float* __restrict__ attn) {
    const int tid = threadIdx.x;
    float4* p = (float4*)(attn + (size_t)blockIdx.x * SEQ);   // 512 float4

    float4 v[2];
    v[0] = p[tid];
    v[1] = p[tid + 256];
    float mx = fmaxf(fmaxf(v[0].x, v[0].y), fmaxf(v[0].z, v[0].w));
    mx = fmaxf(mx, fmaxf(fmaxf(v[1].x, v[1].y), fmaxf(v[1].z, v[1].w)));

    __shared__ float smax[8];
    __shared__ float ssum[8];
#pragma unroll
    for (int o = 16; o > 0; o >>= 1) mx = fmaxf(mx, __shfl_xor_sync(0xffffffffu, mx, o));
    if ((tid & 31) == 0) smax[tid >> 5] = mx;
    __syncthreads();
    float bmx = fmaxf(fmaxf(fmaxf(smax[0], smax[1]), fmaxf(smax[2], smax[3])),
                      fmaxf(fmaxf(smax[4], smax[5]), fmaxf(smax[6], smax[7])));

    float sum = 0.f;
#pragma unroll
    for (int l = 0; l < 2; l++) {
        v[l].x = __expf(v[l].x - bmx); v[l].y = __expf(v[l].y - bmx);
        v[l].z = __expf(v[l].z - bmx); v[l].w = __expf(v[l].w - bmx);
        sum += (v[l].x + v[l].y) + (v[l].z + v[l].w);
    }
#pragma unroll
    for (int o = 16; o > 0; o >>= 1) sum += __shfl_xor_sync(0xffffffffu, sum, o);
    if ((tid & 31) == 0) ssum[tid >> 5] = sum;
    __syncthreads();
    float tot = (ssum[0] + ssum[1]) + (ssum[2] + ssum[3]) +
                (ssum[4] + ssum[5]) + (ssum[6] + ssum[7]);
    float inv = 1.0f / tot;
#pragma unroll
    for (int l = 0; l < 2; l++) {
        v[l].x *= inv; v[l].y *= inv; v[l].z *= inv; v[l].w *= inv;
    }
    p[tid] = v[0];
    p[tid + 256] = v[1];
}

// ---------------------------------------------------------------------------
// ctx = attn @ V per (b,h): tile 128(M) x 64(N), BK=32, 128 threads, 8x8 acc.
// Written directly in merged [B,S,D] layout.
// ---------------------------------------------------------------------------
__global__ void __launch_bounds__(128, 3)
ctx128(const float* __restrict__ attn) {
    __shared__ float As[32][132];   // [k][m] transposed
    __shared__ float Vs[32][68];    // [k][n] natural

    const int bh = blockIdx.y;
    const int b = bh >> 4, h = bh & 15;
    const int mt = blockIdx.x * 128;
    const float* A = attn + (size_t)bh * SEQ * SEQ;
    const float* V = g_v + (size_t)bh * SEQ * DH;

    const int tid = threadIdx.x;
    const int tx = tid & 7;         // n-group: 8 x 8 = 64
    const int ty = tid >> 3;        // m-group: 16 x 8 = 128

    float acc[8][8] = {};
    float4 ra[8], rv[4];

    // ---- load tile k0=0 ----
#pragma unroll
    for (int l = 0; l < 8; l++) {
        int slot = tid + l * 128;               // 0..1023
        int row = slot >> 3, c4 = slot & 7;     // A: 128 rows x 8 float4
        ra[l] = *(const float4*)&A[(size_t)(mt + row) * SEQ + c4 * 4];
    }
#pragma unroll
    for (int l = 0; l < 4; l++) {
        int slot = tid + l * 128;               // 0..511
        int kk = slot >> 4, n4 = slot & 15;     // V: 32 rows x 16 float4
        rv[l] = *(const float4*)&V[(size_t)kk * DH + n4 * 4];
    }
#pragma unroll
    for (int l = 0; l < 8; l++) {
        int slot = tid + l * 128;
        int row = slot >> 3, c4 = slot & 7;
        As[c4 * 4 + 0][row] = ra[l].x; As[c4 * 4 + 1][row] = ra[l].y;
        As[c4 * 4 + 2][row] = ra[l].z; As[c4 * 4 + 3][row] = ra[l].w;
    }
#pragma unroll
    for (int l = 0; l < 4; l++) {
        int slot = tid + l * 128;
        int kk = slot >> 4, n4 = slot & 15;
        *(float4*)&Vs[kk][n4 * 4] = rv[l];
    }
    __syncthreads();

    for (int k0 = 0; k0 < SEQ; k0 += 32) {
        const bool more = (k0 + 32 < SEQ);
        if (more) {
#pragma unroll
            for (int l = 0; l < 8; l++) {
                int slot = tid + l * 128;
                int row = slot >> 3, c4 = slot & 7;
                ra[l] = *(const float4*)&A[(size_t)(mt + row) * SEQ + k0 + 32 + c4 * 4];
            }
#pragma unroll
            for (int l = 0; l < 4; l++) {
                int slot = tid + l * 128;
                int kk = slot >> 4, n4 = slot & 15;
                rv[l] = *(const float4*)&V[(size_t)(k0 + 32 + kk) * DH + n4 * 4];
            }
        }
#pragma unroll
        for (int kk = 0; kk < 32; kk++) {
            float a[8], bv[8];
            *(float4*)&a[0] = *(const float4*)&As[kk][ty * 4];
            *(float4*)&a[4] = *(const float4*)&As[kk][64 + ty * 4];
            *(float4*)&bv[0] = *(const float4*)&Vs[kk][tx * 4];
            *(float4*)&bv[4] = *(const float4*)&Vs[kk][32 + tx * 4];
#pragma unroll
            for (int i = 0; i < 8; i++)
#pragma unroll
                for (int j = 0; j < 8; j++) acc[i][j] += a[i] * bv[j];
        }
        if (more) {
            __syncthreads();
#pragma unroll
            for (int l = 0; l < 8; l++) {
                int slot = tid + l * 128;
                int row = slot >> 3, c4 = slot & 7;
                As[c4 * 4 + 0][row] = ra[l].x; As[c4 * 4 + 1][row] = ra[l].y;
                As[c4 * 4 + 2][row] = ra[l].z; As[c4 * 4 + 3][row] = ra[l].w;
            }
#pragma unroll
            for (int l = 0; l < 4; l++) {
                int slot = tid + l * 128;
                int kk = slot >> 4, n4 = slot & 15;
                *(float4*)&Vs[kk][n4 * 4] = rv[l];
            }
            __syncthreads();
        }
    }

#pragma unroll
    for (int i = 0; i < 8; i++) {
        int s = mt + ((i < 4) ? (ty * 4 + i) : (64 + ty * 4 + i - 4));
#pragma unroll
        for (int jh = 0; jh < 2; jh++) {
            int n0 = (jh ? (32 + tx * 4) : (tx * 4));
            float4 v;
            v.x = acc[i][jh * 4 + 0]; v.y = acc[i][jh * 4 + 1];
            v.z = acc[i][jh * 4 + 2]; v.w = acc[i][jh * 4 + 3];
            *(float4*)&g_ctx[((size_t)b * SEQ + s) * DIM + h * DH + n0] = v;
        }
    }
}

// ---------------------------------------------------------------------------
extern "C" void kernel_launch(void* const* d_in, const int* in_sizes, int n_in,
                              void* d_out, int out_size) {
    const float* x    = (const float*)d_in[0];
    const float* mask = (const float*)d_in[1];
    const float* Wq   = (const float*)d_in[2];
    const float* bq   = (const float*)d_in[3];
    const float* Wk   = (const float*)d_in[4];
    const float* bk   = (const float*)d_in[5];
    const float* Wv   = (const float*)d_in[6];
    const float* bv   = (const float*)d_in[7];
    const float* Wo   = (const float*)d_in[8];
    const float* bo   = (const float*)d_in[9];

    float* out  = (float*)d_out;                       // [B,S,D]
    float* attn = out + (size_t)BS * DIM;              // [B,H,S,S]

    float *qp, *kp, *vp, *cp;
    cudaGetSymbolAddress((void**)&qp, g_q);
    cudaGetSymbolAddress((void**)&kp, g_k);
    cudaGetSymbolAddress((void**)&vp, g_v);
    cudaGetSymbolAddress((void**)&cp, g_ctx);

    dim3 projGrid(DIM / 128, BS / 128);   // (8, 32)
    gemm128<true><<<projGrid, 256>>>(x, Wq, bq, qp, BS, DIM, DIM);
    gemm128<true><<<projGrid, 256>>>(x, Wk, bk, kp, BS, DIM, DIM);
    gemm128<true><<<projGrid, 256>>>(x, Wv, bv, vp, BS, DIM, DIM);

    dim3 logitsGrid(SEQ / 128, SEQ / 128, BB * NH);  // (16, 16, 32)
    logits128<<<logitsGrid, 256>>>(mask, attn);

    softmax_kernel<<<BB * NH * SEQ, 256>>>(attn);

    dim3 ctxGrid(SEQ / 128, BB * NH);   // (16, 32)
    ctx128<<<ctxGrid, 128>>>(attn);

    gemm128<false><<<projGrid, 256>>>(cp, Wo, bo, out, BS, DIM, DIM);
}

// round 6
// speedup vs baseline: 4.3750x; 1.9795x over previous
#include <cuda_runtime.h>
#include <cuda_bf16.h>
#include <stdint.h>

#define BB 2
#define SEQ 2048
#define DIM 1024
#define NH 16
#define DH 64
#define NBH (BB * NH)     // 32
#define BS  (BB * SEQ)    // 4096

// ---- packed split-bf16 scratch (hi in low16, lo in high16) ----
__device__ uint32_t g_wt[(size_t)4 * DIM * DIM];     // W^T packed: [z][n][k]
__device__ uint32_t g_qp[(size_t)NBH * SEQ * DH];    // Q packed [bh][s][dh]
__device__ uint32_t g_kp[(size_t)NBH * SEQ * DH];    // K packed [bh][s][dh]
__device__ uint32_t g_vT[(size_t)NBH * DH * SEQ];    // V^T packed [bh][dh][s]
__device__ float    g_ctx[(size_t)BS * DIM];         // fp32 ctx [B*S][D]

// ============================ low-level helpers ============================
__device__ __forceinline__ uint32_t sptr(const void* p) {
    return (uint32_t)__cvta_generic_to_shared(p);
}

__device__ __forceinline__ void ldm_x4(uint32_t* r, uint32_t addr) {
    asm volatile("ldmatrix.sync.aligned.m8n8.x4.shared.b16 {%0,%1,%2,%3}, [%4];"
                 : "=r"(r[0]), "=r"(r[1]), "=r"(r[2]), "=r"(r[3]) : "r"(addr));
}

__device__ __forceinline__ void mma16816(float* d, const uint32_t* a,
                                         const uint32_t* b) {
    asm volatile(
        "mma.sync.aligned.m16n8k16.row.col.f32.bf16.bf16.f32 "
        "{%0,%1,%2,%3}, {%4,%5,%6,%7}, {%8,%9}, {%0,%1,%2,%3};"
        : "+f"(d[0]), "+f"(d[1]), "+f"(d[2]), "+f"(d[3])
        : "r"(a[0]), "r"(a[1]), "r"(a[2]), "r"(a[3]), "r"(b[0]), "r"(b[1]));
}

__device__ __forceinline__ uint32_t pack_split(float x) {
    __nv_bfloat16 h = __float2bfloat16(x);
    float hf = __bfloat162float(h);
    __nv_bfloat16 l = __float2bfloat16(x - hf);
    return (uint32_t)__bfloat16_as_ushort(h) |
           ((uint32_t)__bfloat16_as_ushort(l) << 16);
}

// store 4 packed values as 8B hi + 8B lo at byte offset off
__device__ __forceinline__ void put_split4(char* Hi, char* Lo, int off,
                                           uint32_t p0, uint32_t p1,
                                           uint32_t p2, uint32_t p3) {
    uint2 h, l;
    h.x = (p0 & 0xffffu) | (p1 << 16);
    h.y = (p2 & 0xffffu) | (p3 << 16);
    l.x = (p0 >> 16) | (p1 & 0xffff0000u);
    l.y = (p2 >> 16) | (p3 & 0xffff0000u);
    *(uint2*)(Hi + off) = h;
    *(uint2*)(Lo + off) = l;
}

// ============================ core warp-MMA block ============================
// Block tile: 128(M) x (NT*8*2)(N), 8 warps (wm=wid>>1 m-offset 32, wn=wid&1).
// A smem: [128][16*KSTEPS] bf16, row stride STRIDE bytes (odd # of 16B units).
// B smem: [n][16*KSTEPS] bf16, same stride. 3-term split accumulate.
template <int STRIDE, int KSTEPS, int NT>
__device__ __forceinline__ void mma_block(const char* Ah, const char* Al,
                                          const char* Bh, const char* Bl,
                                          int wm, int wn, int lane,
                                          float (&acc)[2][NT][4]) {
    uint32_t ahb = sptr(Ah), alb = sptr(Al), bhb = sptr(Bh), blb = sptr(Bl);
#pragma unroll
    for (int ks = 0; ks < KSTEPS; ks++) {
        uint32_t ah[2][4], al[2][4];
#pragma unroll
        for (int mt = 0; mt < 2; mt++) {
            uint32_t off = (uint32_t)(32 * wm + 16 * mt + (lane & 15)) * STRIDE +
                           ((lane >> 4) * 16) + ks * 32;
            ldm_x4(ah[mt], ahb + off);
            ldm_x4(al[mt], alb + off);
        }
#pragma unroll
        for (int np = 0; np < NT / 2; np++) {
            uint32_t boff = (uint32_t)(NT * 8 * wn + np * 16 +
                                       ((lane >> 4) << 3) + (lane & 7)) * STRIDE +
                            (((lane >> 3) & 1) * 16) + ks * 32;
            uint32_t bh[4], bl[4];
            ldm_x4(bh, bhb + boff);
            ldm_x4(bl, blb + boff);
#pragma unroll
            for (int mt = 0; mt < 2; mt++) {
                mma16816(acc[mt][2 * np],     ah[mt], bh);
                mma16816(acc[mt][2 * np],     al[mt], bh);
                mma16816(acc[mt][2 * np],     ah[mt], bl);
                mma16816(acc[mt][2 * np + 1], ah[mt], bh + 2);
                mma16816(acc[mt][2 * np + 1], al[mt], bh + 2);
                mma16816(acc[mt][2 * np + 1], ah[mt], bl + 2);
            }
        }
    }
}

// ============================ weight prep ============================
// g_wt[z][n][k] = pack_split(W_z[k][n])
__global__ void transpose_pack_w(const float* __restrict__ Wq,
                                 const float* __restrict__ Wk,
                                 const float* __restrict__ Wv,
                                 const float* __restrict__ Wo) {
    __shared__ uint32_t t[32][33];
    int z = blockIdx.z;
    const float* W = (z == 0) ? Wq : (z == 1) ? Wk : (z == 2) ? Wv : Wo;
    uint32_t* dst = g_wt + (size_t)z * DIM * DIM;
    int n0 = blockIdx.x * 32, k0 = blockIdx.y * 32;
    int tx = threadIdx.x, ty = threadIdx.y;    // 32 x 8
#pragma unroll
    for (int r = 0; r < 4; r++) {
        int k = k0 + ty + r * 8;
        t[ty + r * 8][tx] = pack_split(W[(size_t)k * DIM + n0 + tx]);
    }
    __syncthreads();
#pragma unroll
    for (int r = 0; r < 4; r++) {
        int n = n0 + ty + r * 8;
        dst[(size_t)n * DIM + k0 + tx] = t[tx][ty + r * 8];
    }
}

// ============================ projections (Q,K,V) ============================
// BK=16, 64 chunks, stride 48B. smem: 2 bufs x (Ah,Al,Bh,Bl) x 6KB = 48KB.
#define P_ST 48
#define P_BUF 24576
__global__ void __launch_bounds__(256)
proj_mma(const float* __restrict__ x, const float* __restrict__ bq,
         const float* __restrict__ bk, const float* __restrict__ bv) {
    extern __shared__ char sm[];
    const int tid = threadIdx.x, lane = tid & 31, wid = tid >> 5;
    const int wm = wid >> 1, wn = wid & 1;
    const int z = blockIdx.z;
    const int bn = blockIdx.x * 128, bm = blockIdx.y * 128;
    const uint32_t* Wt = g_wt + (size_t)z * DIM * DIM + (size_t)bn * DIM;
    const float* Ab = x + (size_t)bm * DIM;
    const float* bias = (z == 0) ? bq : (z == 1) ? bk : bv;

    float acc[2][8][4] = {};
    float4 ra[2];
    uint4  rb[2];

    // indices for staging: 512 float4-slots for A (128r x 4), 512 uint4 for B
    const int r0 = tid >> 2, c0 = tid & 3;            // it=0
    const int r1 = (tid + 256) >> 2, c1 = (tid + 256) & 3;

    auto loadA = [&](int k0) {
        ra[0] = *(const float4*)(Ab + (size_t)r0 * DIM + k0 + c0 * 4);
        ra[1] = *(const float4*)(Ab + (size_t)r1 * DIM + k0 + c1 * 4);
    };
    auto loadB = [&](int k0) {
        rb[0] = *(const uint4*)(Wt + (size_t)r0 * DIM + k0 + c0 * 4);
        rb[1] = *(const uint4*)(Wt + (size_t)r1 * DIM + k0 + c1 * 4);
    };
    auto store = [&](int buf) {
        char* Ah = sm + buf * P_BUF;
        char* Al = Ah + 6144;
        char* Bh = Al + 6144;
        char* Bl = Bh + 6144;
        put_split4(Ah, Al, r0 * P_ST + c0 * 8, pack_split(ra[0].x),
                   pack_split(ra[0].y), pack_split(ra[0].z), pack_split(ra[0].w));
        put_split4(Ah, Al, r1 * P_ST + c1 * 8, pack_split(ra[1].x),
                   pack_split(ra[1].y), pack_split(ra[1].z), pack_split(ra[1].w));
        put_split4(Bh, Bl, r0 * P_ST + c0 * 8, rb[0].x, rb[0].y, rb[0].z, rb[0].w);
        put_split4(Bh, Bl, r1 * P_ST + c1 * 8, rb[1].x, rb[1].y, rb[1].z, rb[1].w);
    };

    loadA(0); loadB(0); store(0);
    __syncthreads();
    for (int c = 0; c < 64; c++) {
        if (c < 63) { loadA((c + 1) * 16); loadB((c + 1) * 16); }
        char* base = sm + (c & 1) * P_BUF;
        mma_block<P_ST, 1, 8>(base, base + 6144, base + 12288, base + 18432,
                              wm, wn, lane, acc);
        if (c < 63) store((c + 1) & 1);
        __syncthreads();
    }

    // epilogue
#pragma unroll
    for (int mt = 0; mt < 2; mt++) {
#pragma unroll
        for (int nt = 0; nt < 8; nt++) {
            int n = bn + 64 * wn + 8 * nt + 2 * (lane & 3);
            float bx = bias[n], by = bias[n + 1];
            int h = n >> 6, dh = n & 63;
            int m0 = bm + 32 * wm + 16 * mt + (lane >> 2);
#pragma unroll
            for (int half = 0; half < 2; half++) {
                int m = m0 + 8 * half;
                int b = m >> 11, s = m & 2047;
                uint32_t pa = pack_split(acc[mt][nt][2 * half + 0] + bx);
                uint32_t pb = pack_split(acc[mt][nt][2 * half + 1] + by);
                if (z < 2) {
                    uint32_t* dst = ((z == 0) ? g_qp : g_kp) +
                        (((size_t)(b * NH + h) * SEQ + s) * DH + dh);
                    *(uint2*)dst = make_uint2(pa, pb);
                } else {
                    uint32_t* dst = g_vT + ((size_t)(b * NH + h) * DH) * SEQ;
                    dst[(size_t)dh * SEQ + s] = pa;
                    dst[(size_t)(dh + 1) * SEQ + s] = pb;
                }
            }
        }
    }
}

// ============================ logits ============================
// 128q x 128k per block, K=64 one-shot. stride 144B. smem 72KB.
#define L_ST 144
#define L_ARR 18432
__global__ void __launch_bounds__(256)
logits_mma(const float* __restrict__ mask, float* __restrict__ attn) {
    extern __shared__ char sm[];
    const int tid = threadIdx.x, lane = tid & 31, wid = tid >> 5;
    const int wm = wid >> 1, wn = wid & 1;
    const int bh = blockIdx.z;
    const int qt = blockIdx.y * 128, kt = blockIdx.x * 128;
    const uint32_t* Q = g_qp + ((size_t)bh * SEQ + qt) * DH;
    const uint32_t* Kp = g_kp + ((size_t)bh * SEQ + kt) * DH;

    char* Qh = sm;
    char* Ql = Qh + L_ARR;
    char* Kh = Ql + L_ARR;
    char* Kl = Kh + L_ARR;

    // stage both tiles: 128 rows x 16 uint4 each
#pragma unroll
    for (int it = 0; it < 8; it++) {
        int idx = it * 256 + tid;
        int row = idx >> 4, c4 = idx & 15;
        int off = row * L_ST + c4 * 8;
        uint4 q = *(const uint4*)(Q + (size_t)row * DH + c4 * 4);
        put_split4(Qh, Ql, off, q.x, q.y, q.z, q.w);
        uint4 k = *(const uint4*)(Kp + (size_t)row * DH + c4 * 4);
        put_split4(Kh, Kl, off, k.x, k.y, k.z, k.w);
    }
    __syncthreads();

    float acc[2][8][4] = {};
    mma_block<L_ST, 4, 8>(Qh, Ql, Kh, Kl, wm, wn, lane, acc);

#pragma unroll
    for (int mt = 0; mt < 2; mt++) {
#pragma unroll
        for (int nt = 0; nt < 8; nt++) {
            int kj = kt + 64 * wn + 8 * nt + 2 * (lane & 3);
            int q0 = qt + 32 * wm + 16 * mt + (lane >> 2);
#pragma unroll
            for (int half = 0; half < 2; half++) {
                int qi = q0 + 8 * half;
                float2 mv = *(const float2*)(mask + (size_t)qi * SEQ + kj);
                float2 o;
                o.x = acc[mt][nt][2 * half + 0] * 0.125f + mv.x * (-1e9f);
                o.y = acc[mt][nt][2 * half + 1] * 0.125f + mv.y * (-1e9f);
                *(float2*)(attn + ((size_t)bh * SEQ + qi) * SEQ + kj) = o;
            }
        }
    }
}

// ============================ softmax (in place) ============================
__global__ void softmax_kernel(float* __restrict__ attn) {
    const int tid = threadIdx.x;
    float4* p = (float4*)(attn + (size_t)blockIdx.x * SEQ);
    float4 v[2];
    v[0] = p[tid];
    v[1] = p[tid + 256];
    float mx = fmaxf(fmaxf(v[0].x, v[0].y), fmaxf(v[0].z, v[0].w));
    mx = fmaxf(mx, fmaxf(fmaxf(v[1].x, v[1].y), fmaxf(v[1].z, v[1].w)));
    __shared__ float smax[8], ssum[8];
#pragma unroll
    for (int o = 16; o > 0; o >>= 1) mx = fmaxf(mx, __shfl_xor_sync(0xffffffffu, mx, o));
    if ((tid & 31) == 0) smax[tid >> 5] = mx;
    __syncthreads();
    float bmx = fmaxf(fmaxf(fmaxf(smax[0], smax[1]), fmaxf(smax[2], smax[3])),
                      fmaxf(fmaxf(smax[4], smax[5]), fmaxf(smax[6], smax[7])));
    float sum = 0.f;
#pragma unroll
    for (int l = 0; l < 2; l++) {
        v[l].x = __expf(v[l].x - bmx); v[l].y = __expf(v[l].y - bmx);
        v[l].z = __expf(v[l].z - bmx); v[l].w = __expf(v[l].w - bmx);
        sum += (v[l].x + v[l].y) + (v[l].z + v[l].w);
    }
#pragma unroll
    for (int o = 16; o > 0; o >>= 1) sum += __shfl_xor_sync(0xffffffffu, sum, o);
    if ((tid & 31) == 0) ssum[tid >> 5] = sum;
    __syncthreads();
    float tot = (ssum[0] + ssum[1]) + (ssum[2] + ssum[3]) +
                (ssum[4] + ssum[5]) + (ssum[6] + ssum[7]);
    float inv = 1.0f / tot;
#pragma unroll
    for (int l = 0; l < 2; l++) {
        v[l].x *= inv; v[l].y *= inv; v[l].z *= inv; v[l].w *= inv;
    }
    p[tid] = v[0];
    p[tid + 256] = v[1];
}

// ============================ ctx = P @ V ============================
// 128(M=s_q) x 64(N=dh) per block, BK=32, 64 chunks, stride 80B, smem 60KB.
#define C_ST 80
#define C_BUF 30720
__global__ void __launch_bounds__(256)
ctx_mma(const float* __restrict__ attn) {
    extern __shared__ char sm[];
    const int tid = threadIdx.x, lane = tid & 31, wid = tid >> 5;
    const int wm = wid >> 1, wn = wid & 1;
    const int bh = blockIdx.y;
    const int b = bh >> 4, h = bh & 15;
    const int mt0 = blockIdx.x * 128;
    const float* A = attn + (size_t)bh * SEQ * SEQ + (size_t)mt0 * SEQ;
    const uint32_t* Bv = g_vT + (size_t)bh * DH * SEQ;

    float acc[2][4][4] = {};
    float4 ra[4];
    uint4  rb[2];

    // A: 1024 float4 slots (128r x 8); B: 512 uint4 slots (64r x 8)
    auto loadA = [&](int k0) {
#pragma unroll
        for (int it = 0; it < 4; it++) {
            int idx = it * 256 + tid;
            int row = idx >> 3, c4 = idx & 7;
            ra[it] = *(const float4*)(A + (size_t)row * SEQ + k0 + c4 * 4);
        }
    };
    auto loadB = [&](int k0) {
#pragma unroll
        for (int it = 0; it < 2; it++) {
            int idx = it * 256 + tid;
            int row = idx >> 3, c4 = idx & 7;
            rb[it] = *(const uint4*)(Bv + (size_t)row * SEQ + k0 + c4 * 4);
        }
    };
    auto store = [&](int buf) {
        char* Ah = sm + buf * C_BUF;
        char* Al = Ah + 10240;
        char* Bh = Al + 10240;
        char* Bl = Bh + 5120;
#pragma unroll
        for (int it = 0; it < 4; it++) {
            int idx = it * 256 + tid;
            int row = idx >> 3, c4 = idx & 7;
            put_split4(Ah, Al, row * C_ST + c4 * 8, pack_split(ra[it].x),
                       pack_split(ra[it].y), pack_split(ra[it].z),
                       pack_split(ra[it].w));
        }
#pragma unroll
        for (int it = 0; it < 2; it++) {
            int idx = it * 256 + tid;
            int row = idx >> 3, c4 = idx & 7;
            put_split4(Bh, Bl, row * C_ST + c4 * 8, rb[it].x, rb[it].y,
                       rb[it].z, rb[it].w);
        }
    };

    loadA(0); loadB(0); store(0);
    __syncthreads();
    for (int c = 0; c < 64; c++) {
        if (c < 63) { loadA((c + 1) * 32); loadB((c + 1) * 32); }
        char* base = sm + (c & 1) * C_BUF;
        mma_block<C_ST, 2, 4>(base, base + 10240, base + 20480, base + 25600,
                              wm, wn, lane, acc);
        if (c < 63) store((c + 1) & 1);
        __syncthreads();
    }

#pragma unroll
    for (int mt = 0; mt < 2; mt++) {
#pragma unroll
        for (int nt = 0; nt < 4; nt++) {
            int nl = 32 * wn + 8 * nt + 2 * (lane & 3);
            int m0 = mt0 + 32 * wm + 16 * mt + (lane >> 2);
#pragma unroll
            for (int half = 0; half < 2; half++) {
                int s = m0 + 8 * half;
                float2 o;
                o.x = acc[mt][nt][2 * half + 0];
                o.y = acc[mt][nt][2 * half + 1];
                *(float2*)(g_ctx + ((size_t)b * SEQ + s) * DIM + h * DH + nl) = o;
            }
        }
    }
}

// ============================ out = ctx @ Wo + bo ============================
__global__ void __launch_bounds__(256)
out_mma(const float* __restrict__ bo, float* __restrict__ out) {
    extern __shared__ char sm[];
    const int tid = threadIdx.x, lane = tid & 31, wid = tid >> 5;
    const int wm = wid >> 1, wn = wid & 1;
    const int bn = blockIdx.x * 128, bm = blockIdx.y * 128;
    const uint32_t* Wt = g_wt + (size_t)3 * DIM * DIM + (size_t)bn * DIM;
    const float* Ab = g_ctx + (size_t)bm * DIM;

    float acc[2][8][4] = {};
    float4 ra[2];
    uint4  rb[2];
    const int r0 = tid >> 2, c0 = tid & 3;
    const int r1 = (tid + 256) >> 2, c1 = (tid + 256) & 3;

    auto loadA = [&](int k0) {
        ra[0] = *(const float4*)(Ab + (size_t)r0 * DIM + k0 + c0 * 4);
        ra[1] = *(const float4*)(Ab + (size_t)r1 * DIM + k0 + c1 * 4);
    };
    auto loadB = [&](int k0) {
        rb[0] = *(const uint4*)(Wt + (size_t)r0 * DIM + k0 + c0 * 4);
        rb[1] = *(const uint4*)(Wt + (size_t)r1 * DIM + k0 + c1 * 4);
    };
    auto store = [&](int buf) {
        char* Ah = sm + buf * P_BUF;
        char* Al = Ah + 6144;
        char* Bh = Al + 6144;
        char* Bl = Bh + 6144;
        put_split4(Ah, Al, r0 * P_ST + c0 * 8, pack_split(ra[0].x),
                   pack_split(ra[0].y), pack_split(ra[0].z), pack_split(ra[0].w));
        put_split4(Ah, Al, r1 * P_ST + c1 * 8, pack_split(ra[1].x),
                   pack_split(ra[1].y), pack_split(ra[1].z), pack_split(ra[1].w));
        put_split4(Bh, Bl, r0 * P_ST + c0 * 8, rb[0].x, rb[0].y, rb[0].z, rb[0].w);
        put_split4(Bh, Bl, r1 * P_ST + c1 * 8, rb[1].x, rb[1].y, rb[1].z, rb[1].w);
    };

    loadA(0); loadB(0); store(0);
    __syncthreads();
    for (int c = 0; c < 64; c++) {
        if (c < 63) { loadA((c + 1) * 16); loadB((c + 1) * 16); }
        char* base = sm + (c & 1) * P_BUF;
        mma_block<P_ST, 1, 8>(base, base + 6144, base + 12288, base + 18432,
                              wm, wn, lane, acc);
        if (c < 63) store((c + 1) & 1);
        __syncthreads();
    }

#pragma unroll
    for (int mt = 0; mt < 2; mt++) {
#pragma unroll
        for (int nt = 0; nt < 8; nt++) {
            int n = bn + 64 * wn + 8 * nt + 2 * (lane & 3);
            float bx = bo[n], by = bo[n + 1];
            int m0 = bm + 32 * wm + 16 * mt + (lane >> 2);
#pragma unroll
            for (int half = 0; half < 2; half++) {
                int m = m0 + 8 * half;
                float2 o;
                o.x = acc[mt][nt][2 * half + 0] + bx;
                o.y = acc[mt][nt][2 * half + 1] + by;
                *(float2*)(out + (size_t)m * DIM + n) = o;
            }
        }
    }
}

// ============================ launcher ============================
extern "C" void kernel_launch(void* const* d_in, const int* in_sizes, int n_in,
                              void* d_out, int out_size) {
    const float* x    = (const float*)d_in[0];
    const float* mask = (const float*)d_in[1];
    const float* Wq   = (const float*)d_in[2];
    const float* bq   = (const float*)d_in[3];
    const float* Wk   = (const float*)d_in[4];
    const float* bk   = (const float*)d_in[5];
    const float* Wv   = (const float*)d_in[6];
    const float* bv   = (const float*)d_in[7];
    const float* Wo   = (const float*)d_in[8];
    const float* bo   = (const float*)d_in[9];

    float* out  = (float*)d_out;                 // [B,S,D]
    float* attn = out + (size_t)BS * DIM;        // [B,H,S,S]

    const int projSmem = 2 * P_BUF;              // 48 KB
    const int logSmem  = 4 * L_ARR;              // 72 KB
    const int ctxSmem  = 2 * C_BUF;              // 60 KB
    cudaFuncSetAttribute(proj_mma,   cudaFuncAttributeMaxDynamicSharedMemorySize, projSmem);
    cudaFuncSetAttribute(logits_mma, cudaFuncAttributeMaxDynamicSharedMemorySize, logSmem);
    cudaFuncSetAttribute(ctx_mma,    cudaFuncAttributeMaxDynamicSharedMemorySize, ctxSmem);
    cudaFuncSetAttribute(out_mma,    cudaFuncAttributeMaxDynamicSharedMemorySize, projSmem);

    transpose_pack_w<<<dim3(32, 32, 4), dim3(32, 8)>>>(Wq, Wk, Wv, Wo);
    proj_mma<<<dim3(8, 32, 3), 256, projSmem>>>(x, bq, bk, bv);
    logits_mma<<<dim3(16, 16, 32), 256, logSmem>>>(mask, attn);
    softmax_kernel<<<NBH * SEQ, 256>>>(attn);
    ctx_mma<<<dim3(16, 32), 256, ctxSmem>>>(attn);
    out_mma<<<dim3(8, 32), 256, projSmem>>>(bo, out);
}

// round 7
// speedup vs baseline: 4.5040x; 1.0295x over previous
#include <cuda_runtime.h>
#include <cuda_bf16.h>
#include <stdint.h>

#define BB 2
#define SEQ 2048
#define DIM 1024
#define NH 16
#define DH 64
#define NBH (BB * NH)     // 32
#define BS  (BB * SEQ)    // 4096

// ---- packed split-bf16 scratch (hi in low16, lo in high16) ----
__device__ uint32_t g_wt[(size_t)4 * DIM * DIM];     // W^T packed: [z][n][k]
__device__ uint32_t g_qp[(size_t)NBH * SEQ * DH];    // Q packed [bh][s][dh]
__device__ uint32_t g_kp[(size_t)NBH * SEQ * DH];    // K packed [bh][s][dh]
__device__ uint32_t g_vT[(size_t)NBH * DH * SEQ];    // V^T packed [bh][dh][s]
__device__ float    g_ctx[(size_t)BS * DIM];         // fp32 ctx [B*S][D]
__device__ float2   g_ps[(size_t)NBH * SEQ * 16];    // partial softmax stats (m, s)

// ============================ low-level helpers ============================
__device__ __forceinline__ uint32_t sptr(const void* p) {
    return (uint32_t)__cvta_generic_to_shared(p);
}

__device__ __forceinline__ void ldm_x4(uint32_t* r, uint32_t addr) {
    asm volatile("ldmatrix.sync.aligned.m8n8.x4.shared.b16 {%0,%1,%2,%3}, [%4];"
                 : "=r"(r[0]), "=r"(r[1]), "=r"(r[2]), "=r"(r[3]) : "r"(addr));
}

__device__ __forceinline__ void mma16816(float* d, const uint32_t* a,
                                         const uint32_t* b) {
    asm volatile(
        "mma.sync.aligned.m16n8k16.row.col.f32.bf16.bf16.f32 "
        "{%0,%1,%2,%3}, {%4,%5,%6,%7}, {%8,%9}, {%0,%1,%2,%3};"
        : "+f"(d[0]), "+f"(d[1]), "+f"(d[2]), "+f"(d[3])
        : "r"(a[0]), "r"(a[1]), "r"(a[2]), "r"(a[3]), "r"(b[0]), "r"(b[1]));
}

__device__ __forceinline__ uint32_t pack_split(float x) {
    __nv_bfloat16 h = __float2bfloat16(x);
    float hf = __bfloat162float(h);
    __nv_bfloat16 l = __float2bfloat16(x - hf);
    return (uint32_t)__bfloat16_as_ushort(h) |
           ((uint32_t)__bfloat16_as_ushort(l) << 16);
}

// store 4 packed values as 8B hi + 8B lo at byte offset off
__device__ __forceinline__ void put_split4(char* Hi, char* Lo, int off,
                                           uint32_t p0, uint32_t p1,
                                           uint32_t p2, uint32_t p3) {
    uint2 h, l;
    h.x = (p0 & 0xffffu) | (p1 << 16);
    h.y = (p2 & 0xffffu) | (p3 << 16);
    l.x = (p0 >> 16) | (p1 & 0xffff0000u);
    l.y = (p2 >> 16) | (p3 & 0xffff0000u);
    *(uint2*)(Hi + off) = h;
    *(uint2*)(Lo + off) = l;
}

// ============================ core warp-MMA block ============================
// Block tile: 128(M) x (NT*8*2)(N), 8 warps (wm=wid>>1 m-offset 32, wn=wid&1).
// A smem: [128][16*KSTEPS] bf16, row stride STRIDE bytes (odd # of 16B units).
// B smem: [n][16*KSTEPS] bf16, same stride. 3-term split accumulate.
template <int STRIDE, int KSTEPS, int NT>
__device__ __forceinline__ void mma_block(const char* Ah, const char* Al,
                                          const char* Bh, const char* Bl,
                                          int wm, int wn, int lane,
                                          float (&acc)[2][NT][4]) {
    uint32_t ahb = sptr(Ah), alb = sptr(Al), bhb = sptr(Bh), blb = sptr(Bl);
#pragma unroll
    for (int ks = 0; ks < KSTEPS; ks++) {
        uint32_t ah[2][4], al[2][4];
#pragma unroll
        for (int mt = 0; mt < 2; mt++) {
            uint32_t off = (uint32_t)(32 * wm + 16 * mt + (lane & 15)) * STRIDE +
                           ((lane >> 4) * 16) + ks * 32;
            ldm_x4(ah[mt], ahb + off);
            ldm_x4(al[mt], alb + off);
        }
#pragma unroll
        for (int np = 0; np < NT / 2; np++) {
            uint32_t boff = (uint32_t)(NT * 8 * wn + np * 16 +
                                       ((lane >> 4) << 3) + (lane & 7)) * STRIDE +
                            (((lane >> 3) & 1) * 16) + ks * 32;
            uint32_t bh[4], bl[4];
            ldm_x4(bh, bhb + boff);
            ldm_x4(bl, blb + boff);
#pragma unroll
            for (int mt = 0; mt < 2; mt++) {
                mma16816(acc[mt][2 * np],     ah[mt], bh);
                mma16816(acc[mt][2 * np],     al[mt], bh);
                mma16816(acc[mt][2 * np],     ah[mt], bl);
                mma16816(acc[mt][2 * np + 1], ah[mt], bh + 2);
                mma16816(acc[mt][2 * np + 1], al[mt], bh + 2);
                mma16816(acc[mt][2 * np + 1], ah[mt], bl + 2);
            }
        }
    }
}

// ============================ weight prep ============================
// g_wt[z][n][k] = pack_split(W_z[k][n])
__global__ void transpose_pack_w(const float* __restrict__ Wq,
                                 const float* __restrict__ Wk,
                                 const float* __restrict__ Wv,
                                 const float* __restrict__ Wo) {
    __shared__ uint32_t t[32][33];
    int z = blockIdx.z;
    const float* W = (z == 0) ? Wq : (z == 1) ? Wk : (z == 2) ? Wv : Wo;
    uint32_t* dst = g_wt + (size_t)z * DIM * DIM;
    int n0 = blockIdx.x * 32, k0 = blockIdx.y * 32;
    int tx = threadIdx.x, ty = threadIdx.y;    // 32 x 8
#pragma unroll
    for (int r = 0; r < 4; r++) {
        int k = k0 + ty + r * 8;
        t[ty + r * 8][tx] = pack_split(W[(size_t)k * DIM + n0 + tx]);
    }
    __syncthreads();
#pragma unroll
    for (int r = 0; r < 4; r++) {
        int n = n0 + ty + r * 8;
        dst[(size_t)n * DIM + k0 + tx] = t[tx][ty + r * 8];
    }
}

// ============================ projections (Q,K,V) & out ============================
// BK=32, 32 chunks, stride 80B. smem: 2 bufs x 4 arrays x 10KB = 80KB.
#define P_ST 80
#define P_ARR 10240
#define P_BUF (4 * P_ARR)
__global__ void __launch_bounds__(256)
proj_mma(const float* __restrict__ x, const float* __restrict__ bq,
         const float* __restrict__ bk, const float* __restrict__ bv) {
    extern __shared__ char sm[];
    const int tid = threadIdx.x, lane = tid & 31, wid = tid >> 5;
    const int wm = wid >> 1, wn = wid & 1;
    const int z = blockIdx.z;
    const int bn = blockIdx.x * 128, bm = blockIdx.y * 128;
    const uint32_t* Wt = g_wt + (size_t)z * DIM * DIM + (size_t)bn * DIM;
    const float* Ab = x + (size_t)bm * DIM;
    const float* bias = (z == 0) ? bq : (z == 1) ? bk : bv;

    float acc[2][8][4] = {};
    float4 ra[4];
    uint4  rb[4];

    auto loadA = [&](int k0) {
#pragma unroll
        for (int it = 0; it < 4; it++) {
            int idx = it * 256 + tid;
            int row = idx >> 3, c4 = idx & 7;
            ra[it] = *(const float4*)(Ab + (size_t)row * DIM + k0 + c4 * 4);
        }
    };
    auto loadB = [&](int k0) {
#pragma unroll
        for (int it = 0; it < 4; it++) {
            int idx = it * 256 + tid;
            int row = idx >> 3, c4 = idx & 7;
            rb[it] = *(const uint4*)(Wt + (size_t)row * DIM + k0 + c4 * 4);
        }
    };
    auto store = [&](int buf) {
        char* Ah = sm + buf * P_BUF;
        char* Al = Ah + P_ARR;
        char* Bh = Al + P_ARR;
        char* Bl = Bh + P_ARR;
#pragma unroll
        for (int it = 0; it < 4; it++) {
            int idx = it * 256 + tid;
            int row = idx >> 3, c4 = idx & 7;
            put_split4(Ah, Al, row * P_ST + c4 * 8, pack_split(ra[it].x),
                       pack_split(ra[it].y), pack_split(ra[it].z),
                       pack_split(ra[it].w));
            put_split4(Bh, Bl, row * P_ST + c4 * 8, rb[it].x, rb[it].y,
                       rb[it].z, rb[it].w);
        }
    };

    loadA(0); loadB(0); store(0);
    __syncthreads();
    for (int c = 0; c < 32; c++) {
        if (c < 31) { loadA((c + 1) * 32); loadB((c + 1) * 32); }
        char* base = sm + (c & 1) * P_BUF;
        mma_block<P_ST, 2, 8>(base, base + P_ARR, base + 2 * P_ARR,
                              base + 3 * P_ARR, wm, wn, lane, acc);
        if (c < 31) store((c + 1) & 1);
        __syncthreads();
    }

    // epilogue
#pragma unroll
    for (int mt = 0; mt < 2; mt++) {
#pragma unroll
        for (int nt = 0; nt < 8; nt++) {
            int n = bn + 64 * wn + 8 * nt + 2 * (lane & 3);
            float bx = bias[n], by = bias[n + 1];
            int h = n >> 6, dh = n & 63;
            int m0 = bm + 32 * wm + 16 * mt + (lane >> 2);
#pragma unroll
            for (int half = 0; half < 2; half++) {
                int m = m0 + 8 * half;
                int b = m >> 11, s = m & 2047;
                uint32_t pa = pack_split(acc[mt][nt][2 * half + 0] + bx);
                uint32_t pb = pack_split(acc[mt][nt][2 * half + 1] + by);
                if (z < 2) {
                    uint32_t* dst = ((z == 0) ? g_qp : g_kp) +
                        (((size_t)(b * NH + h) * SEQ + s) * DH + dh);
                    *(uint2*)dst = make_uint2(pa, pb);
                } else {
                    uint32_t* dst = g_vT + ((size_t)(b * NH + h) * DH) * SEQ;
                    dst[(size_t)dh * SEQ + s] = pa;
                    dst[(size_t)(dh + 1) * SEQ + s] = pb;
                }
            }
        }
    }
}

__global__ void __launch_bounds__(256)
out_mma(const float* __restrict__ bo, float* __restrict__ out) {
    extern __shared__ char sm[];
    const int tid = threadIdx.x, lane = tid & 31, wid = tid >> 5;
    const int wm = wid >> 1, wn = wid & 1;
    const int bn = blockIdx.x * 128, bm = blockIdx.y * 128;
    const uint32_t* Wt = g_wt + (size_t)3 * DIM * DIM + (size_t)bn * DIM;
    const float* Ab = g_ctx + (size_t)bm * DIM;

    float acc[2][8][4] = {};
    float4 ra[4];
    uint4  rb[4];

    auto loadA = [&](int k0) {
#pragma unroll
        for (int it = 0; it < 4; it++) {
            int idx = it * 256 + tid;
            int row = idx >> 3, c4 = idx & 7;
            ra[it] = *(const float4*)(Ab + (size_t)row * DIM + k0 + c4 * 4);
        }
    };
    auto loadB = [&](int k0) {
#pragma unroll
        for (int it = 0; it < 4; it++) {
            int idx = it * 256 + tid;
            int row = idx >> 3, c4 = idx & 7;
            rb[it] = *(const uint4*)(Wt + (size_t)row * DIM + k0 + c4 * 4);
        }
    };
    auto store = [&](int buf) {
        char* Ah = sm + buf * P_BUF;
        char* Al = Ah + P_ARR;
        char* Bh = Al + P_ARR;
        char* Bl = Bh + P_ARR;
#pragma unroll
        for (int it = 0; it < 4; it++) {
            int idx = it * 256 + tid;
            int row = idx >> 3, c4 = idx & 7;
            put_split4(Ah, Al, row * P_ST + c4 * 8, pack_split(ra[it].x),
                       pack_split(ra[it].y), pack_split(ra[it].z),
                       pack_split(ra[it].w));
            put_split4(Bh, Bl, row * P_ST + c4 * 8, rb[it].x, rb[it].y,
                       rb[it].z, rb[it].w);
        }
    };

    loadA(0); loadB(0); store(0);
    __syncthreads();
    for (int c = 0; c < 32; c++) {
        if (c < 31) { loadA((c + 1) * 32); loadB((c + 1) * 32); }
        char* base = sm + (c & 1) * P_BUF;
        mma_block<P_ST, 2, 8>(base, base + P_ARR, base + 2 * P_ARR,
                              base + 3 * P_ARR, wm, wn, lane, acc);
        if (c < 31) store((c + 1) & 1);
        __syncthreads();
    }

#pragma unroll
    for (int mt = 0; mt < 2; mt++) {
#pragma unroll
        for (int nt = 0; nt < 8; nt++) {
            int n = bn + 64 * wn + 8 * nt + 2 * (lane & 3);
            float bx = bo[n], by = bo[n + 1];
            int m0 = bm + 32 * wm + 16 * mt + (lane >> 2);
#pragma unroll
            for (int half = 0; half < 2; half++) {
                int m = m0 + 8 * half;
                float2 o;
                o.x = acc[mt][nt][2 * half + 0] + bx;
                o.y = acc[mt][nt][2 * half + 1] + by;
                *(float2*)(out + (size_t)m * DIM + n) = o;
            }
        }
    }
}

// ============================ logits + partial softmax stats ============================
// 128q x 128k per block, K=64 one-shot. stride 144B. smem 72KB + 1KB stats.
#define L_ST 144
#define L_ARR 18432
__global__ void __launch_bounds__(256)
logits_mma(const float* __restrict__ mask, float* __restrict__ attn) {
    extern __shared__ char sm[];
    __shared__ float2 sstat[128][2];
    const int tid = threadIdx.x, lane = tid & 31, wid = tid >> 5;
    const int wm = wid >> 1, wn = wid & 1;
    const int bh = blockIdx.z;
    const int qt = blockIdx.y * 128, kt = blockIdx.x * 128;
    const uint32_t* Q = g_qp + ((size_t)bh * SEQ + qt) * DH;
    const uint32_t* Kp = g_kp + ((size_t)bh * SEQ + kt) * DH;

    char* Qh = sm;
    char* Ql = Qh + L_ARR;
    char* Kh = Ql + L_ARR;
    char* Kl = Kh + L_ARR;

#pragma unroll
    for (int it = 0; it < 8; it++) {
        int idx = it * 256 + tid;
        int row = idx >> 4, c4 = idx & 15;
        int off = row * L_ST + c4 * 8;
        uint4 q = *(const uint4*)(Q + (size_t)row * DH + c4 * 4);
        put_split4(Qh, Ql, off, q.x, q.y, q.z, q.w);
        uint4 k = *(const uint4*)(Kp + (size_t)row * DH + c4 * 4);
        put_split4(Kh, Kl, off, k.x, k.y, k.z, k.w);
    }
    __syncthreads();

    float acc[2][8][4] = {};
    mma_block<L_ST, 4, 8>(Qh, Ql, Kh, Kl, wm, wn, lane, acc);

    const float scale = 0.125f;
#pragma unroll
    for (int mt = 0; mt < 2; mt++) {
#pragma unroll
        for (int half = 0; half < 2; half++) {
            int rl = 32 * wm + 16 * mt + (lane >> 2) + 8 * half;
            int qi = qt + rl;
            const float* mrow = mask + (size_t)qi * SEQ;
            float* arow = attn + ((size_t)bh * SEQ + qi) * SEQ;
            float m = -1e30f;
#pragma unroll
            for (int nt = 0; nt < 8; nt++) {
                int kj = kt + 64 * wn + 8 * nt + 2 * (lane & 3);
                float2 mv = *(const float2*)(mrow + kj);
                float vx = acc[mt][nt][2 * half + 0] * scale + mv.x * (-1e9f);
                float vy = acc[mt][nt][2 * half + 1] * scale + mv.y * (-1e9f);
                *(float2*)(arow + kj) = make_float2(vx, vy);
                m = fmaxf(m, fmaxf(vx, vy));
            }
            m = fmaxf(m, __shfl_xor_sync(0xffffffffu, m, 1));
            m = fmaxf(m, __shfl_xor_sync(0xffffffffu, m, 2));
            float s = 0.f;
#pragma unroll
            for (int nt = 0; nt < 8; nt++) {
                int kj = kt + 64 * wn + 8 * nt + 2 * (lane & 3);
                float2 mv = *(const float2*)(mrow + kj);
                float vx = acc[mt][nt][2 * half + 0] * scale + mv.x * (-1e9f);
                float vy = acc[mt][nt][2 * half + 1] * scale + mv.y * (-1e9f);
                s += __expf(vx - m) + __expf(vy - m);
            }
            s += __shfl_xor_sync(0xffffffffu, s, 1);
            s += __shfl_xor_sync(0xffffffffu, s, 2);
            if ((lane & 3) == 0) sstat[rl][wn] = make_float2(m, s);
        }
    }
    __syncthreads();

    if (tid < 128) {
        float2 a = sstat[tid][0], b = sstat[tid][1];
        float m = fmaxf(a.x, b.x);
        float s = a.y * __expf(a.x - m) + b.y * __expf(b.x - m);
        g_ps[((size_t)bh * SEQ + qt + tid) * 16 + blockIdx.x] = make_float2(m, s);
    }
}

// ============================ ctx: softmax-normalize + write attn + P @ V ============================
// 128(M=s_q) x 64(N=dh) per block, BK=32, 64 chunks, stride 80B, smem 60KB.
#define C_ST 80
#define C_BUF 30720
__global__ void __launch_bounds__(256)
ctx_mma(float* __restrict__ attn) {
    extern __shared__ char sm[];
    __shared__ float rowC[128];
    const int tid = threadIdx.x, lane = tid & 31, wid = tid >> 5;
    const int wm = wid >> 1, wn = wid & 1;
    const int bh = blockIdx.y;
    const int b = bh >> 4, h = bh & 15;
    const int mt0 = blockIdx.x * 128;
    float* A = attn + (size_t)bh * SEQ * SEQ + (size_t)mt0 * SEQ;
    const uint32_t* Bv = g_vT + (size_t)bh * DH * SEQ;

    // combine the 16 partial stats per row: C = m_row + ln(Z_row)
    if (tid < 128) {
        const float2* ps = &g_ps[((size_t)bh * SEQ + mt0 + tid) * 16];
        float m = -1e30f;
#pragma unroll
        for (int t = 0; t < 16; t++) m = fmaxf(m, ps[t].x);
        float z = 0.f;
#pragma unroll
        for (int t = 0; t < 16; t++) z += ps[t].y * __expf(ps[t].x - m);
        rowC[tid] = m + __logf(z);
    }
    __syncthreads();

    // per-thread cached row constants for the 4 staging rows
    float Cw[4];
#pragma unroll
    for (int it = 0; it < 4; it++) Cw[it] = rowC[(it * 256 + tid) >> 3];

    float acc[2][4][4] = {};
    float4 ra[4];
    uint4  rb[2];

    auto loadA = [&](int k0) {
#pragma unroll
        for (int it = 0; it < 4; it++) {
            int idx = it * 256 + tid;
            int row = idx >> 3, c4 = idx & 7;
            ra[it] = *(const float4*)(A + (size_t)row * SEQ + k0 + c4 * 4);
        }
    };
    auto loadB = [&](int k0) {
#pragma unroll
        for (int it = 0; it < 2; it++) {
            int idx = it * 256 + tid;
            int row = idx >> 3, c4 = idx & 7;
            rb[it] = *(const uint4*)(Bv + (size_t)row * SEQ + k0 + c4 * 4);
        }
    };
    // normalize (exp), write normalized attn, pack-split into smem
    auto store = [&](int buf, int k0) {
        char* Ah = sm + buf * C_BUF;
        char* Al = Ah + 10240;
        char* Bh = Al + 10240;
        char* Bl = Bh + 5120;
#pragma unroll
        for (int it = 0; it < 4; it++) {
            int idx = it * 256 + tid;
            int row = idx >> 3, c4 = idx & 7;
            float4 p;
            p.x = __expf(ra[it].x - Cw[it]);
            p.y = __expf(ra[it].y - Cw[it]);
            p.z = __expf(ra[it].z - Cw[it]);
            p.w = __expf(ra[it].w - Cw[it]);
            *(float4*)(A + (size_t)row * SEQ + k0 + c4 * 4) = p;
            put_split4(Ah, Al, row * C_ST + c4 * 8, pack_split(p.x),
                       pack_split(p.y), pack_split(p.z), pack_split(p.w));
        }
#pragma unroll
        for (int it = 0; it < 2; it++) {
            int idx = it * 256 + tid;
            int row = idx >> 3, c4 = idx & 7;
            put_split4(Bh, Bl, row * C_ST + c4 * 8, rb[it].x, rb[it].y,
                       rb[it].z, rb[it].w);
        }
    };

    loadA(0); loadB(0); store(0, 0);
    __syncthreads();
    for (int c = 0; c < 64; c++) {
        if (c < 63) { loadA((c + 1) * 32); loadB((c + 1) * 32); }
        char* base = sm + (c & 1) * C_BUF;
        mma_block<C_ST, 2, 4>(base, base + 10240, base + 20480, base + 25600,
                              wm, wn, lane, acc);
        if (c < 63) store((c + 1) & 1, (c + 1) * 32);
        __syncthreads();
    }

#pragma unroll
    for (int mt = 0; mt < 2; mt++) {
#pragma unroll
        for (int nt = 0; nt < 4; nt++) {
            int nl = 32 * wn + 8 * nt + 2 * (lane & 3);
            int m0 = mt0 + 32 * wm + 16 * mt + (lane >> 2);
#pragma unroll
            for (int half = 0; half < 2; half++) {
                int s = m0 + 8 * half;
                float2 o;
                o.x = acc[mt][nt][2 * half + 0];
                o.y = acc[mt][nt][2 * half + 1];
                *(float2*)(g_ctx + ((size_t)b * SEQ + s) * DIM + h * DH + nl) = o;
            }
        }
    }
}

// ============================ launcher ============================
extern "C" void kernel_launch(void* const* d_in, const int* in_sizes, int n_in,
                              void* d_out, int out_size) {
    const float* x    = (const float*)d_in[0];
    const float* mask = (const float*)d_in[1];
    const float* Wq   = (const float*)d_in[2];
    const float* bq   = (const float*)d_in[3];
    const float* Wk   = (const float*)d_in[4];
    const float* bk   = (const float*)d_in[5];
    const float* Wv   = (const float*)d_in[6];
    const float* bv   = (const float*)d_in[7];
    const float* Wo   = (const float*)d_in[8];
    const float* bo   = (const float*)d_in[9];

    float* out  = (float*)d_out;                 // [B,S,D]
    float* attn = out + (size_t)BS * DIM;        // [B,H,S,S]

    const int projSmem = 2 * P_BUF;              // 80 KB
    const int logSmem  = 4 * L_ARR;              // 72 KB
    const int ctxSmem  = 2 * C_BUF;              // 60 KB
    cudaFuncSetAttribute(proj_mma,   cudaFuncAttributeMaxDynamicSharedMemorySize, projSmem);
    cudaFuncSetAttribute(logits_mma, cudaFuncAttributeMaxDynamicSharedMemorySize, logSmem);
    cudaFuncSetAttribute(ctx_mma,    cudaFuncAttributeMaxDynamicSharedMemorySize, ctxSmem);
    cudaFuncSetAttribute(out_mma,    cudaFuncAttributeMaxDynamicSharedMemorySize, projSmem);

    transpose_pack_w<<<dim3(32, 32, 4), dim3(32, 8)>>>(Wq, Wk, Wv, Wo);
    proj_mma<<<dim3(8, 32, 3), 256, projSmem>>>(x, bq, bk, bv);
    logits_mma<<<dim3(16, 16, 32), 256, logSmem>>>(mask, attn);
    ctx_mma<<<dim3(16, 32), 256, ctxSmem>>>(attn);
    out_mma<<<dim3(8, 32), 256, projSmem>>>(bo, out);
}

// round 8
// speedup vs baseline: 4.8539x; 1.0777x over previous
#include <cuda_runtime.h>
#include <cuda_fp16.h>
#include <stdint.h>

#define BB 2
#define SEQ 2048
#define DIM 1024
#define NH 16
#define DH 64
#define NBH (BB * NH)     // 32
#define BS  (BB * SEQ)    // 4096

// ---- scratch ----
__device__ __half   g_wt[(size_t)4 * DIM * DIM];     // W^T fp16-hi: [z][n][k]
__device__ uint32_t g_qp[(size_t)NBH * SEQ * DH];    // Q split-packed (hi|lo) [bh][s][dh]
__device__ __half   g_kp[(size_t)NBH * SEQ * DH];    // K fp16-hi [bh][s][dh]
__device__ __half   g_vT[(size_t)NBH * DH * SEQ];    // V^T fp16-hi [bh][dh][s]
__device__ float    g_ctx[(size_t)BS * DIM];         // fp32 ctx [B*S][D]
__device__ float2   g_ps[(size_t)NBH * SEQ * 16];    // partial softmax stats (m, s)

// ============================ low-level helpers ============================
__device__ __forceinline__ uint32_t sptr(const void* p) {
    return (uint32_t)__cvta_generic_to_shared(p);
}

__device__ __forceinline__ void ldm_x4(uint32_t* r, uint32_t addr) {
    asm volatile("ldmatrix.sync.aligned.m8n8.x4.shared.b16 {%0,%1,%2,%3}, [%4];"
                 : "=r"(r[0]), "=r"(r[1]), "=r"(r[2]), "=r"(r[3]) : "r"(addr));
}

__device__ __forceinline__ void mma16816(float* d, const uint32_t* a,
                                         const uint32_t* b) {
    asm volatile(
        "mma.sync.aligned.m16n8k16.row.col.f32.f16.f16.f32 "
        "{%0,%1,%2,%3}, {%4,%5,%6,%7}, {%8,%9}, {%0,%1,%2,%3};"
        : "+f"(d[0]), "+f"(d[1]), "+f"(d[2]), "+f"(d[3])
        : "r"(a[0]), "r"(a[1]), "r"(a[2]), "r"(a[3]), "r"(b[0]), "r"(b[1]));
}

// split fp32 -> fp16 hi (low 16) + fp16 lo (high 16)
__device__ __forceinline__ uint32_t pack_split(float x) {
    __half h = __float2half(x);
    float hf = __half2float(h);
    __half l = __float2half(x - hf);
    return (uint32_t)__half_as_ushort(h) | ((uint32_t)__half_as_ushort(l) << 16);
}

// store 4 packed values as 8B hi + 8B lo at byte offset off
__device__ __forceinline__ void put_split4(char* Hi, char* Lo, int off,
                                           uint32_t p0, uint32_t p1,
                                           uint32_t p2, uint32_t p3) {
    uint2 h, l;
    h.x = (p0 & 0xffffu) | (p1 << 16);
    h.y = (p2 & 0xffffu) | (p3 << 16);
    l.x = (p0 >> 16) | (p1 & 0xffff0000u);
    l.y = (p2 >> 16) | (p3 & 0xffff0000u);
    *(uint2*)(Hi + off) = h;
    *(uint2*)(Lo + off) = l;
}

// ============================ core warp-MMA block (2-term) ============================
// Block tile: 128(M) x (NT*8*2)(N), 8 warps (wm=wid>>1 m-offset 32, wn=wid&1).
// A: hi+lo arrays; B: hi only. acc += ah*bh + al*bh.
template <int STRIDE, int KSTEPS, int NT>
__device__ __forceinline__ void mma_block(const char* Ah, const char* Al,
                                          const char* Bh,
                                          int wm, int wn, int lane,
                                          float (&acc)[2][NT][4]) {
    uint32_t ahb = sptr(Ah), alb = sptr(Al), bhb = sptr(Bh);
#pragma unroll
    for (int ks = 0; ks < KSTEPS; ks++) {
        uint32_t ah[2][4], al[2][4];
#pragma unroll
        for (int mt = 0; mt < 2; mt++) {
            uint32_t off = (uint32_t)(32 * wm + 16 * mt + (lane & 15)) * STRIDE +
                           ((lane >> 4) * 16) + ks * 32;
            ldm_x4(ah[mt], ahb + off);
            ldm_x4(al[mt], alb + off);
        }
#pragma unroll
        for (int np = 0; np < NT / 2; np++) {
            uint32_t boff = (uint32_t)(NT * 8 * wn + np * 16 +
                                       ((lane >> 4) << 3) + (lane & 7)) * STRIDE +
                            (((lane >> 3) & 1) * 16) + ks * 32;
            uint32_t bh[4];
            ldm_x4(bh, bhb + boff);
#pragma unroll
            for (int mt = 0; mt < 2; mt++) {
                mma16816(acc[mt][2 * np],     ah[mt], bh);
                mma16816(acc[mt][2 * np],     al[mt], bh);
                mma16816(acc[mt][2 * np + 1], ah[mt], bh + 2);
                mma16816(acc[mt][2 * np + 1], al[mt], bh + 2);
            }
        }
    }
}

// ============================ weight prep ============================
// g_wt[z][n][k] = fp16(W_z[k][n])
__global__ void transpose_pack_w(const float* __restrict__ Wq,
                                 const float* __restrict__ Wk,
                                 const float* __restrict__ Wv,
                                 const float* __restrict__ Wo) {
    __shared__ __half t[32][33];
    int z = blockIdx.z;
    const float* W = (z == 0) ? Wq : (z == 1) ? Wk : (z == 2) ? Wv : Wo;
    __half* dst = g_wt + (size_t)z * DIM * DIM;
    int n0 = blockIdx.x * 32, k0 = blockIdx.y * 32;
    int tx = threadIdx.x, ty = threadIdx.y;    // 32 x 8
#pragma unroll
    for (int r = 0; r < 4; r++) {
        int k = k0 + ty + r * 8;
        t[ty + r * 8][tx] = __float2half(W[(size_t)k * DIM + n0 + tx]);
    }
    __syncthreads();
#pragma unroll
    for (int r = 0; r < 4; r++) {
        int n = n0 + ty + r * 8;
        dst[(size_t)n * DIM + k0 + tx] = t[tx][ty + r * 8];
    }
}

// ============================ projections (Q,K,V) & out ============================
// BK=32, 32 chunks, stride 80B. smem: 2 bufs x (Ah,Al,Bh) x 10KB = 60KB.
#define P_ST 80
#define P_ARR 10240
#define P_BUF (3 * P_ARR)
__global__ void __launch_bounds__(256)
proj_mma(const float* __restrict__ x, const float* __restrict__ bq,
         const float* __restrict__ bk, const float* __restrict__ bv) {
    extern __shared__ char sm[];
    const int tid = threadIdx.x, lane = tid & 31, wid = tid >> 5;
    const int wm = wid >> 1, wn = wid & 1;
    const int z = blockIdx.z;
    const int bn = blockIdx.x * 128, bm = blockIdx.y * 128;
    const __half* Wt = g_wt + (size_t)z * DIM * DIM + (size_t)bn * DIM;
    const float* Ab = x + (size_t)bm * DIM;
    const float* bias = (z == 0) ? bq : (z == 1) ? bk : bv;

    float acc[2][8][4] = {};
    float4 ra[4];
    uint4  rb[2];

    auto loadA = [&](int k0) {
#pragma unroll
        for (int it = 0; it < 4; it++) {
            int idx = it * 256 + tid;
            int row = idx >> 3, c4 = idx & 7;
            ra[it] = *(const float4*)(Ab + (size_t)row * DIM + k0 + c4 * 4);
        }
    };
    auto loadB = [&](int k0) {   // 128 n-rows x 32 k halfs = 512 uint4
#pragma unroll
        for (int it = 0; it < 2; it++) {
            int idx = it * 256 + tid;
            int row = idx >> 2, c4 = idx & 3;
            rb[it] = *(const uint4*)(Wt + (size_t)row * DIM + k0 + c4 * 8);
        }
    };
    auto store = [&](int buf) {
        char* Ah = sm + buf * P_BUF;
        char* Al = Ah + P_ARR;
        char* Bh = Al + P_ARR;
#pragma unroll
        for (int it = 0; it < 4; it++) {
            int idx = it * 256 + tid;
            int row = idx >> 3, c4 = idx & 7;
            put_split4(Ah, Al, row * P_ST + c4 * 8, pack_split(ra[it].x),
                       pack_split(ra[it].y), pack_split(ra[it].z),
                       pack_split(ra[it].w));
        }
#pragma unroll
        for (int it = 0; it < 2; it++) {
            int idx = it * 256 + tid;
            int row = idx >> 2, c4 = idx & 3;
            *(uint4*)(Bh + row * P_ST + c4 * 16) = rb[it];
        }
    };

    loadA(0); loadB(0); store(0);
    __syncthreads();
    for (int c = 0; c < 32; c++) {
        if (c < 31) { loadA((c + 1) * 32); loadB((c + 1) * 32); }
        char* base = sm + (c & 1) * P_BUF;
        mma_block<P_ST, 2, 8>(base, base + P_ARR, base + 2 * P_ARR,
                              wm, wn, lane, acc);
        if (c < 31) store((c + 1) & 1);
        __syncthreads();
    }

    // epilogue
#pragma unroll
    for (int mt = 0; mt < 2; mt++) {
#pragma unroll
        for (int nt = 0; nt < 8; nt++) {
            int n = bn + 64 * wn + 8 * nt + 2 * (lane & 3);
            float bx = bias[n], by = bias[n + 1];
            int h = n >> 6, dh = n & 63;
            int m0 = bm + 32 * wm + 16 * mt + (lane >> 2);
#pragma unroll
            for (int half = 0; half < 2; half++) {
                int m = m0 + 8 * half;
                int b = m >> 11, s = m & 2047;
                float va = acc[mt][nt][2 * half + 0] + bx;
                float vb = acc[mt][nt][2 * half + 1] + by;
                if (z == 0) {
                    uint32_t* dst = g_qp +
                        (((size_t)(b * NH + h) * SEQ + s) * DH + dh);
                    *(uint2*)dst = make_uint2(pack_split(va), pack_split(vb));
                } else if (z == 1) {
                    __half* dst = g_kp +
                        (((size_t)(b * NH + h) * SEQ + s) * DH + dh);
                    *(__half2*)dst = __floats2half2_rn(va, vb);
                } else {
                    __half* dst = g_vT + ((size_t)(b * NH + h) * DH) * SEQ;
                    dst[(size_t)dh * SEQ + s] = __float2half(va);
                    dst[(size_t)(dh + 1) * SEQ + s] = __float2half(vb);
                }
            }
        }
    }
}

__global__ void __launch_bounds__(256)
out_mma(const float* __restrict__ bo, float* __restrict__ out) {
    extern __shared__ char sm[];
    const int tid = threadIdx.x, lane = tid & 31, wid = tid >> 5;
    const int wm = wid >> 1, wn = wid & 1;
    const int bn = blockIdx.x * 128, bm = blockIdx.y * 128;
    const __half* Wt = g_wt + (size_t)3 * DIM * DIM + (size_t)bn * DIM;
    const float* Ab = g_ctx + (size_t)bm * DIM;

    float acc[2][8][4] = {};
    float4 ra[4];
    uint4  rb[2];

    auto loadA = [&](int k0) {
#pragma unroll
        for (int it = 0; it < 4; it++) {
            int idx = it * 256 + tid;
            int row = idx >> 3, c4 = idx & 7;
            ra[it] = *(const float4*)(Ab + (size_t)row * DIM + k0 + c4 * 4);
        }
    };
    auto loadB = [&](int k0) {
#pragma unroll
        for (int it = 0; it < 2; it++) {
            int idx = it * 256 + tid;
            int row = idx >> 2, c4 = idx & 3;
            rb[it] = *(const uint4*)(Wt + (size_t)row * DIM + k0 + c4 * 8);
        }
    };
    auto store = [&](int buf) {
        char* Ah = sm + buf * P_BUF;
        char* Al = Ah + P_ARR;
        char* Bh = Al + P_ARR;
#pragma unroll
        for (int it = 0; it < 4; it++) {
            int idx = it * 256 + tid;
            int row = idx >> 3, c4 = idx & 7;
            put_split4(Ah, Al, row * P_ST + c4 * 8, pack_split(ra[it].x),
                       pack_split(ra[it].y), pack_split(ra[it].z),
                       pack_split(ra[it].w));
        }
#pragma unroll
        for (int it = 0; it < 2; it++) {
            int idx = it * 256 + tid;
            int row = idx >> 2, c4 = idx & 3;
            *(uint4*)(Bh + row * P_ST + c4 * 16) = rb[it];
        }
    };

    loadA(0); loadB(0); store(0);
    __syncthreads();
    for (int c = 0; c < 32; c++) {
        if (c < 31) { loadA((c + 1) * 32); loadB((c + 1) * 32); }
        char* base = sm + (c & 1) * P_BUF;
        mma_block<P_ST, 2, 8>(base, base + P_ARR, base + 2 * P_ARR,
                              wm, wn, lane, acc);
        if (c < 31) store((c + 1) & 1);
        __syncthreads();
    }

#pragma unroll
    for (int mt = 0; mt < 2; mt++) {
#pragma unroll
        for (int nt = 0; nt < 8; nt++) {
            int n = bn + 64 * wn + 8 * nt + 2 * (lane & 3);
            float bx = bo[n], by = bo[n + 1];
            int m0 = bm + 32 * wm + 16 * mt + (lane >> 2);
#pragma unroll
            for (int half = 0; half < 2; half++) {
                int m = m0 + 8 * half;
                float2 o;
                o.x = acc[mt][nt][2 * half + 0] + bx;
                o.y = acc[mt][nt][2 * half + 1] + by;
                *(float2*)(out + (size_t)m * DIM + n) = o;
            }
        }
    }
}

// ============================ logits + partial softmax stats ============================
// 128q x 128k per block, K=64 one-shot. stride 144B. smem 54KB + stats.
#define L_ST 144
#define L_ARR 18432
__global__ void __launch_bounds__(256)
logits_mma(const float* __restrict__ mask, float* __restrict__ attn) {
    extern __shared__ char sm[];
    __shared__ float2 sstat[128][2];
    const int tid = threadIdx.x, lane = tid & 31, wid = tid >> 5;
    const int wm = wid >> 1, wn = wid & 1;
    const int bh = blockIdx.z;
    const int qt = blockIdx.y * 128, kt = blockIdx.x * 128;
    const uint32_t* Q = g_qp + ((size_t)bh * SEQ + qt) * DH;
    const __half* Kp = g_kp + ((size_t)bh * SEQ + kt) * DH;

    char* Qh = sm;
    char* Ql = Qh + L_ARR;
    char* Kh = Ql + L_ARR;

    // Q: 128 rows x 16 uint4 (packed u32)
#pragma unroll
    for (int it = 0; it < 8; it++) {
        int idx = it * 256 + tid;
        int row = idx >> 4, c4 = idx & 15;
        uint4 q = *(const uint4*)(Q + (size_t)row * DH + c4 * 4);
        put_split4(Qh, Ql, row * L_ST + c4 * 8, q.x, q.y, q.z, q.w);
    }
    // K: 128 rows x 8 uint4 (halfs)
#pragma unroll
    for (int it = 0; it < 4; it++) {
        int idx = it * 256 + tid;
        int row = idx >> 3, c4 = idx & 7;
        uint4 k = *(const uint4*)(Kp + (size_t)row * DH + c4 * 8);
        *(uint4*)(Kh + row * L_ST + c4 * 16) = k;
    }
    __syncthreads();

    float acc[2][8][4] = {};
    mma_block<L_ST, 4, 8>(Qh, Ql, Kh, wm, wn, lane, acc);

    const float scale = 0.125f;
#pragma unroll
    for (int mt = 0; mt < 2; mt++) {
#pragma unroll
        for (int half = 0; half < 2; half++) {
            int rl = 32 * wm + 16 * mt + (lane >> 2) + 8 * half;
            int qi = qt + rl;
            const float* mrow = mask + (size_t)qi * SEQ;
            float* arow = attn + ((size_t)bh * SEQ + qi) * SEQ;
            float m = -1e30f;
#pragma unroll
            for (int nt = 0; nt < 8; nt++) {
                int kj = kt + 64 * wn + 8 * nt + 2 * (lane & 3);
                float2 mv = *(const float2*)(mrow + kj);
                float vx = acc[mt][nt][2 * half + 0] * scale + mv.x * (-1e9f);
                float vy = acc[mt][nt][2 * half + 1] * scale + mv.y * (-1e9f);
                *(float2*)(arow + kj) = make_float2(vx, vy);
                m = fmaxf(m, fmaxf(vx, vy));
            }
            m = fmaxf(m, __shfl_xor_sync(0xffffffffu, m, 1));
            m = fmaxf(m, __shfl_xor_sync(0xffffffffu, m, 2));
            float s = 0.f;
#pragma unroll
            for (int nt = 0; nt < 8; nt++) {
                int kj = kt + 64 * wn + 8 * nt + 2 * (lane & 3);
                float2 mv = *(const float2*)(mrow + kj);
                float vx = acc[mt][nt][2 * half + 0] * scale + mv.x * (-1e9f);
                float vy = acc[mt][nt][2 * half + 1] * scale + mv.y * (-1e9f);
                s += __expf(vx - m) + __expf(vy - m);
            }
            s += __shfl_xor_sync(0xffffffffu, s, 1);
            s += __shfl_xor_sync(0xffffffffu, s, 2);
            if ((lane & 3) == 0) sstat[rl][wn] = make_float2(m, s);
        }
    }
    __syncthreads();

    if (tid < 128) {
        float2 a = sstat[tid][0], b = sstat[tid][1];
        float m = fmaxf(a.x, b.x);
        float s = a.y * __expf(a.x - m) + b.y * __expf(b.x - m);
        g_ps[((size_t)bh * SEQ + qt + tid) * 16 + blockIdx.x] = make_float2(m, s);
    }
}

// ============================ ctx: softmax-normalize + write attn + P @ V ============================
// 128(M=s_q) x 64(N=dh) per block, BK=32, 64 chunks, stride 80B, smem 50KB.
#define C_ST 80
#define C_AARR 10240
#define C_BARR 5120
#define C_BUF (2 * C_AARR + C_BARR)
__global__ void __launch_bounds__(256, 3)
ctx_mma(float* __restrict__ attn) {
    extern __shared__ char sm[];
    __shared__ float rowC[128];
    const int tid = threadIdx.x, lane = tid & 31, wid = tid >> 5;
    const int wm = wid >> 1, wn = wid & 1;
    const int bh = blockIdx.y;
    const int b = bh >> 4, h = bh & 15;
    const int mt0 = blockIdx.x * 128;
    float* A = attn + (size_t)bh * SEQ * SEQ + (size_t)mt0 * SEQ;
    const __half* Bv = g_vT + (size_t)bh * DH * SEQ;

    // combine the 16 partial stats per row: C = m_row + ln(Z_row)
    if (tid < 128) {
        const float2* ps = &g_ps[((size_t)bh * SEQ + mt0 + tid) * 16];
        float m = -1e30f;
#pragma unroll
        for (int t = 0; t < 16; t++) m = fmaxf(m, ps[t].x);
        float z = 0.f;
#pragma unroll
        for (int t = 0; t < 16; t++) z += ps[t].y * __expf(ps[t].x - m);
        rowC[tid] = m + __logf(z);
    }
    __syncthreads();

    float Cw[4];
#pragma unroll
    for (int it = 0; it < 4; it++) Cw[it] = rowC[(it * 256 + tid) >> 3];

    float acc[2][4][4] = {};
    float4 ra[4];
    uint4  rb;

    auto loadA = [&](int k0) {
#pragma unroll
        for (int it = 0; it < 4; it++) {
            int idx = it * 256 + tid;
            int row = idx >> 3, c4 = idx & 7;
            ra[it] = *(const float4*)(A + (size_t)row * SEQ + k0 + c4 * 4);
        }
    };
    auto loadB = [&](int k0) {   // 64 rows x 32 halfs = 256 uint4
        int row = tid >> 2, c4 = tid & 3;
        rb = *(const uint4*)(Bv + (size_t)row * SEQ + k0 + c4 * 8);
    };
    auto store = [&](int buf, int k0) {
        char* Ah = sm + buf * C_BUF;
        char* Al = Ah + C_AARR;
        char* Bh = Al + C_AARR;
#pragma unroll
        for (int it = 0; it < 4; it++) {
            int idx = it * 256 + tid;
            int row = idx >> 3, c4 = idx & 7;
            float4 p;
            p.x = __expf(ra[it].x - Cw[it]);
            p.y = __expf(ra[it].y - Cw[it]);
            p.z = __expf(ra[it].z - Cw[it]);
            p.w = __expf(ra[it].w - Cw[it]);
            *(float4*)(A + (size_t)row * SEQ + k0 + c4 * 4) = p;
            put_split4(Ah, Al, row * C_ST + c4 * 8, pack_split(p.x),
                       pack_split(p.y), pack_split(p.z), pack_split(p.w));
        }
        int row = tid >> 2, c4 = tid & 3;
        *(uint4*)(Bh + row * C_ST + c4 * 16) = rb;
    };

    loadA(0); loadB(0); store(0, 0);
    __syncthreads();
    for (int c = 0; c < 64; c++) {
        if (c < 63) { loadA((c + 1) * 32); loadB((c + 1) * 32); }
        char* base = sm + (c & 1) * C_BUF;
        mma_block<C_ST, 2, 4>(base, base + C_AARR, base + 2 * C_AARR,
                              wm, wn, lane, acc);
        if (c < 63) store((c + 1) & 1, (c + 1) * 32);
        __syncthreads();
    }

#pragma unroll
    for (int mt = 0; mt < 2; mt++) {
#pragma unroll
        for (int nt = 0; nt < 4; nt++) {
            int nl = 32 * wn + 8 * nt + 2 * (lane & 3);
            int m0 = mt0 + 32 * wm + 16 * mt + (lane >> 2);
#pragma unroll
            for (int half = 0; half < 2; half++) {
                int s = m0 + 8 * half;
                float2 o;
                o.x = acc[mt][nt][2 * half + 0];
                o.y = acc[mt][nt][2 * half + 1];
                *(float2*)(g_ctx + ((size_t)b * SEQ + s) * DIM + h * DH + nl) = o;
            }
        }
    }
}

// ============================ launcher ============================
extern "C" void kernel_launch(void* const* d_in, const int* in_sizes, int n_in,
                              void* d_out, int out_size) {
    const float* x    = (const float*)d_in[0];
    const float* mask = (const float*)d_in[1];
    const float* Wq   = (const float*)d_in[2];
    const float* bq   = (const float*)d_in[3];
    const float* Wk   = (const float*)d_in[4];
    const float* bk   = (const float*)d_in[5];
    const float* Wv   = (const float*)d_in[6];
    const float* bv   = (const float*)d_in[7];
    const float* Wo   = (const float*)d_in[8];
    const float* bo   = (const float*)d_in[9];

    float* out  = (float*)d_out;                 // [B,S,D]
    float* attn = out + (size_t)BS * DIM;        // [B,H,S,S]

    const int projSmem = 2 * P_BUF;              // 60 KB
    const int logSmem  = 3 * L_ARR;              // 54 KB
    const int ctxSmem  = 2 * C_BUF;              // 50 KB
    cudaFuncSetAttribute(proj_mma,   cudaFuncAttributeMaxDynamicSharedMemorySize, projSmem);
    cudaFuncSetAttribute(logits_mma, cudaFuncAttributeMaxDynamicSharedMemorySize, logSmem);
    cudaFuncSetAttribute(ctx_mma,    cudaFuncAttributeMaxDynamicSharedMemorySize, ctxSmem);
    cudaFuncSetAttribute(out_mma,    cudaFuncAttributeMaxDynamicSharedMemorySize, projSmem);

    transpose_pack_w<<<dim3(32, 32, 4), dim3(32, 8)>>>(Wq, Wk, Wv, Wo);
    proj_mma<<<dim3(8, 32, 3), 256, projSmem>>>(x, bq, bk, bv);
    logits_mma<<<dim3(16, 16, 32), 256, logSmem>>>(mask, attn);
    ctx_mma<<<dim3(16, 32), 256, ctxSmem>>>(attn);
    out_mma<<<dim3(8, 32), 256, projSmem>>>(bo, out);
}

// round 9
// speedup vs baseline: 4.9273x; 1.0151x over previous
#include <cuda_runtime.h>
#include <cuda_fp16.h>
#include <stdint.h>

#define BB 2
#define SEQ 2048
#define DIM 1024
#define NH 16
#define DH 64
#define NBH (BB * NH)     // 32
#define BS  (BB * SEQ)    // 4096

// ---- fp16 scratch ----
__device__ __half g_xh[(size_t)BS * DIM];           // x hi
__device__ __half g_xl[(size_t)BS * DIM];           // x lo
__device__ __half g_wt[(size_t)4 * DIM * DIM];      // W^T fp16-hi: [z][n][k]
__device__ __half g_qh[(size_t)NBH * SEQ * DH];     // Q hi [bh][s][dh]
__device__ __half g_ql[(size_t)NBH * SEQ * DH];     // Q lo
__device__ __half g_kh[(size_t)NBH * SEQ * DH];     // K hi
__device__ __half g_vn[(size_t)NBH * SEQ * DH];     // V hi [bh][s][dh]
__device__ __half g_vT[(size_t)NBH * DH * SEQ];     // V^T hi [bh][dh][s]
__device__ __half g_ch[(size_t)BS * DIM];           // ctx hi [B*S][D]
__device__ __half g_cl[(size_t)BS * DIM];           // ctx lo
__device__ float2 g_ps[(size_t)NBH * SEQ * 32];     // partial softmax stats (m, s)

// ============================ low-level helpers ============================
__device__ __forceinline__ uint32_t sptr(const void* p) {
    return (uint32_t)__cvta_generic_to_shared(p);
}

__device__ __forceinline__ void ldm_x4(uint32_t* r, uint32_t addr) {
    asm volatile("ldmatrix.sync.aligned.m8n8.x4.shared.b16 {%0,%1,%2,%3}, [%4];"
                 : "=r"(r[0]), "=r"(r[1]), "=r"(r[2]), "=r"(r[3]) : "r"(addr));
}

__device__ __forceinline__ void mma16816(float* d, const uint32_t* a,
                                         const uint32_t* b) {
    asm volatile(
        "mma.sync.aligned.m16n8k16.row.col.f32.f16.f16.f32 "
        "{%0,%1,%2,%3}, {%4,%5,%6,%7}, {%8,%9}, {%0,%1,%2,%3};"
        : "+f"(d[0]), "+f"(d[1]), "+f"(d[2]), "+f"(d[3])
        : "r"(a[0]), "r"(a[1]), "r"(a[2]), "r"(a[3]), "r"(b[0]), "r"(b[1]));
}

// split fp32 -> fp16 hi + fp16 lo, packed (hi low16, lo high16)
__device__ __forceinline__ uint32_t pack_split(float x) {
    __half h = __float2half(x);
    float hf = __half2float(h);
    __half l = __float2half(x - hf);
    return (uint32_t)__half_as_ushort(h) | ((uint32_t)__half_as_ushort(l) << 16);
}

// store 4 packed values as 8B hi + 8B lo at byte offset off
__device__ __forceinline__ void put_split4(char* Hi, char* Lo, int off,
                                           uint32_t p0, uint32_t p1,
                                           uint32_t p2, uint32_t p3) {
    uint2 h, l;
    h.x = (p0 & 0xffffu) | (p1 << 16);
    h.y = (p2 & 0xffffu) | (p3 << 16);
    l.x = (p0 >> 16) | (p1 & 0xffff0000u);
    l.y = (p2 >> 16) | (p3 & 0xffff0000u);
    *(uint2*)(Hi + off) = h;
    *(uint2*)(Lo + off) = l;
}

// ============================ core warp-MMA block (2-term) ============================
// A: hi+lo arrays; B: hi only. acc += ah*bh + al*bh.
// M covered by wm (32 rows) x 2 mt(16); N covered by wn (NT*8) x NT n8-tiles.
template <int STRIDE, int KSTEPS, int NT>
__device__ __forceinline__ void mma_block(const char* Ah, const char* Al,
                                          const char* Bh,
                                          int wm, int wn, int lane,
                                          float (&acc)[2][NT][4]) {
    uint32_t ahb = sptr(Ah), alb = sptr(Al), bhb = sptr(Bh);
#pragma unroll
    for (int ks = 0; ks < KSTEPS; ks++) {
        uint32_t ah[2][4], al[2][4];
#pragma unroll
        for (int mt = 0; mt < 2; mt++) {
            uint32_t off = (uint32_t)(32 * wm + 16 * mt + (lane & 15)) * STRIDE +
                           ((lane >> 4) * 16) + ks * 32;
            ldm_x4(ah[mt], ahb + off);
            ldm_x4(al[mt], alb + off);
        }
#pragma unroll
        for (int np = 0; np < NT / 2; np++) {
            uint32_t boff = (uint32_t)(NT * 8 * wn + np * 16 +
                                       ((lane >> 4) << 3) + (lane & 7)) * STRIDE +
                            (((lane >> 3) & 1) * 16) + ks * 32;
            uint32_t bh[4];
            ldm_x4(bh, bhb + boff);
#pragma unroll
            for (int mt = 0; mt < 2; mt++) {
                mma16816(acc[mt][2 * np],     ah[mt], bh);
                mma16816(acc[mt][2 * np],     al[mt], bh);
                mma16816(acc[mt][2 * np + 1], ah[mt], bh + 2);
                mma16816(acc[mt][2 * np + 1], al[mt], bh + 2);
            }
        }
    }
}

// ============================ prep kernels ============================
__global__ void split_x(const float* __restrict__ x) {
    size_t i = ((size_t)blockIdx.x * blockDim.x + threadIdx.x) * 4;
    float4 f = *(const float4*)(x + i);
    uint32_t p0 = pack_split(f.x), p1 = pack_split(f.y);
    uint32_t p2 = pack_split(f.z), p3 = pack_split(f.w);
    uint2 h, l;
    h.x = (p0 & 0xffffu) | (p1 << 16);
    h.y = (p2 & 0xffffu) | (p3 << 16);
    l.x = (p0 >> 16) | (p1 & 0xffff0000u);
    l.y = (p2 >> 16) | (p3 & 0xffff0000u);
    *(uint2*)(g_xh + i) = h;
    *(uint2*)(g_xl + i) = l;
}

// g_wt[z][n][k] = fp16(W_z[k][n])
__global__ void transpose_pack_w(const float* __restrict__ Wq,
                                 const float* __restrict__ Wk,
                                 const float* __restrict__ Wv,
                                 const float* __restrict__ Wo) {
    __shared__ __half t[32][33];
    int z = blockIdx.z;
    const float* W = (z == 0) ? Wq : (z == 1) ? Wk : (z == 2) ? Wv : Wo;
    __half* dst = g_wt + (size_t)z * DIM * DIM;
    int n0 = blockIdx.x * 32, k0 = blockIdx.y * 32;
    int tx = threadIdx.x, ty = threadIdx.y;    // 32 x 8
#pragma unroll
    for (int r = 0; r < 4; r++) {
        int k = k0 + ty + r * 8;
        t[ty + r * 8][tx] = __float2half(W[(size_t)k * DIM + n0 + tx]);
    }
    __syncthreads();
#pragma unroll
    for (int r = 0; r < 4; r++) {
        int n = n0 + ty + r * 8;
        dst[(size_t)n * DIM + k0 + tx] = t[tx][ty + r * 8];
    }
}

// g_vT[bh][dh][s] = g_vn[bh][s][dh]
__global__ void transpose_v() {
    __shared__ __half t[32][33];
    int bh = blockIdx.z;
    int s0 = blockIdx.x * 32, d0 = blockIdx.y * 32;
    int tx = threadIdx.x, ty = threadIdx.y;    // 32 x 8
    const __half* src = g_vn + (size_t)bh * SEQ * DH;
    __half* dst = g_vT + (size_t)bh * DH * SEQ;
#pragma unroll
    for (int r = 0; r < 4; r++) {
        int s = s0 + ty + r * 8;
        t[ty + r * 8][tx] = src[(size_t)s * DH + d0 + tx];
    }
    __syncthreads();
#pragma unroll
    for (int r = 0; r < 4; r++) {
        int d = d0 + ty + r * 8;
        dst[(size_t)d * SEQ + s0 + tx] = t[tx][ty + r * 8];
    }
}

// ============================ projections (Q,K,V) & out ============================
// BK=32, 32 chunks, stride 80B. smem: 2 bufs x (Ah,Al,Bh) x 10KB = 60KB.
#define P_ST 80
#define P_ARR 10240
#define P_BUF (3 * P_ARR)

// shared GEMM body: C[bm:bm+128][bn:bn+128] = Asplit @ Bt^T  (K = DIM)
template <typename EPI>
__device__ __forceinline__ void gemm128_body(const __half* Xh, const __half* Xl,
                                             const __half* Bt, char* sm, EPI epi) {
    const int tid = threadIdx.x, lane = tid & 31, wid = tid >> 5;
    const int wm = wid >> 1, wn = wid & 1;

    float acc[2][8][4] = {};
    uint4 rah[2], ral[2], rb[2];

    auto loadA = [&](int k0) {
#pragma unroll
        for (int it = 0; it < 2; it++) {
            int idx = it * 256 + tid;
            int row = idx >> 2, c4 = idx & 3;    // 128 rows x 4 uint4
            rah[it] = *(const uint4*)(Xh + (size_t)row * DIM + k0 + c4 * 8);
            ral[it] = *(const uint4*)(Xl + (size_t)row * DIM + k0 + c4 * 8);
        }
    };
    auto loadB = [&](int k0) {
#pragma unroll
        for (int it = 0; it < 2; it++) {
            int idx = it * 256 + tid;
            int row = idx >> 2, c4 = idx & 3;
            rb[it] = *(const uint4*)(Bt + (size_t)row * DIM + k0 + c4 * 8);
        }
    };
    auto store = [&](int buf) {
        char* Ah = sm + buf * P_BUF;
        char* Al = Ah + P_ARR;
        char* Bh = Al + P_ARR;
#pragma unroll
        for (int it = 0; it < 2; it++) {
            int idx = it * 256 + tid;
            int row = idx >> 2, c4 = idx & 3;
            *(uint4*)(Ah + row * P_ST + c4 * 16) = rah[it];
            *(uint4*)(Al + row * P_ST + c4 * 16) = ral[it];
            *(uint4*)(Bh + row * P_ST + c4 * 16) = rb[it];
        }
    };

    loadA(0); loadB(0); store(0);
    __syncthreads();
    for (int c = 0; c < 32; c++) {
        if (c < 31) { loadA((c + 1) * 32); loadB((c + 1) * 32); }
        char* base = sm + (c & 1) * P_BUF;
        mma_block<P_ST, 2, 8>(base, base + P_ARR, base + 2 * P_ARR,
                              wm, wn, lane, acc);
        if (c < 31) store((c + 1) & 1);
        __syncthreads();
    }
    epi(acc, wm, wn, lane);
}

__global__ void __launch_bounds__(256, 2)
proj_mma(const float* __restrict__ bq, const float* __restrict__ bk,
         const float* __restrict__ bv) {
    extern __shared__ char sm[];
    const int z = blockIdx.z;
    const int bn = blockIdx.x * 128, bm = blockIdx.y * 128;
    const __half* Bt = g_wt + (size_t)z * DIM * DIM + (size_t)bn * DIM;
    const float* bias = (z == 0) ? bq : (z == 1) ? bk : bv;

    gemm128_body(g_xh + (size_t)bm * DIM, g_xl + (size_t)bm * DIM, Bt, sm,
        [&](float (&acc)[2][8][4], int wm, int wn, int lane) {
#pragma unroll
            for (int mt = 0; mt < 2; mt++) {
#pragma unroll
                for (int nt = 0; nt < 8; nt++) {
                    int n = bn + 64 * wn + 8 * nt + 2 * (lane & 3);
                    float bx = bias[n], by = bias[n + 1];
                    int h = n >> 6, dh = n & 63;
                    int m0 = bm + 32 * wm + 16 * mt + (lane >> 2);
#pragma unroll
                    for (int half = 0; half < 2; half++) {
                        int m = m0 + 8 * half;
                        int b = m >> 11, s = m & 2047;
                        float va = acc[mt][nt][2 * half + 0] + bx;
                        float vb = acc[mt][nt][2 * half + 1] + by;
                        size_t off = ((size_t)(b * NH + h) * SEQ + s) * DH + dh;
                        __half ha = __float2half(va);
                        __half hb = __float2half(vb);
                        if (z == 0) {
                            __half la = __float2half(va - __half2float(ha));
                            __half lb = __float2half(vb - __half2float(hb));
                            *(__half2*)(g_qh + off) = __halves2half2(ha, hb);
                            *(__half2*)(g_ql + off) = __halves2half2(la, lb);
                        } else if (z == 1) {
                            *(__half2*)(g_kh + off) = __halves2half2(ha, hb);
                        } else {
                            *(__half2*)(g_vn + off) = __halves2half2(ha, hb);
                        }
                    }
                }
            }
        });
}

__global__ void __launch_bounds__(256, 2)
out_mma(const float* __restrict__ bo, float* __restrict__ out) {
    extern __shared__ char sm[];
    const int bn = blockIdx.x * 128, bm = blockIdx.y * 128;
    const __half* Bt = g_wt + (size_t)3 * DIM * DIM + (size_t)bn * DIM;

    gemm128_body(g_ch + (size_t)bm * DIM, g_cl + (size_t)bm * DIM, Bt, sm,
        [&](float (&acc)[2][8][4], int wm, int wn, int lane) {
#pragma unroll
            for (int mt = 0; mt < 2; mt++) {
#pragma unroll
                for (int nt = 0; nt < 8; nt++) {
                    int n = bn + 64 * wn + 8 * nt + 2 * (lane & 3);
                    float bx = bo[n], by = bo[n + 1];
                    int m0 = bm + 32 * wm + 16 * mt + (lane >> 2);
#pragma unroll
                    for (int half = 0; half < 2; half++) {
                        int m = m0 + 8 * half;
                        float2 o;
                        o.x = acc[mt][nt][2 * half + 0] + bx;
                        o.y = acc[mt][nt][2 * half + 1] + by;
                        *(float2*)(out + (size_t)m * DIM + n) = o;
                    }
                }
            }
        });
}

// ============================ logits + partial softmax stats ============================
// 128q x 64k per block, contraction K=64 one-shot. stride 144B. smem 45KB.
#define L_ST 144
#define L_QARR 18432          // 128 x 144
#define L_KARR 9216           // 64 x 144
__global__ void __launch_bounds__(256, 3)
logits_mma(const float* __restrict__ mask, float* __restrict__ attn) {
    extern __shared__ char sm[];
    __shared__ float2 sstat[128][2];
    const int tid = threadIdx.x, lane = tid & 31, wid = tid >> 5;
    const int wm = wid >> 1, wn = wid & 1;
    const int bh = blockIdx.z;
    const int qt = blockIdx.y * 128, kt = blockIdx.x * 64;

    char* Qh = sm;
    char* Ql = Qh + L_QARR;
    char* Kh = Ql + L_QARR;

    // Q: 128 rows x 8 uint4 per array
#pragma unroll
    for (int it = 0; it < 4; it++) {
        int idx = it * 256 + tid;
        int row = idx >> 3, c4 = idx & 7;
        size_t src = ((size_t)bh * SEQ + qt + row) * DH + c4 * 8;
        *(uint4*)(Qh + row * L_ST + c4 * 16) = *(const uint4*)(g_qh + src);
        *(uint4*)(Ql + row * L_ST + c4 * 16) = *(const uint4*)(g_ql + src);
    }
    // K: 64 rows x 8 uint4
#pragma unroll
    for (int it = 0; it < 2; it++) {
        int idx = it * 256 + tid;
        int row = idx >> 3, c4 = idx & 7;
        size_t src = ((size_t)bh * SEQ + kt + row) * DH + c4 * 8;
        *(uint4*)(Kh + row * L_ST + c4 * 16) = *(const uint4*)(g_kh + src);
    }
    __syncthreads();

    float acc[2][4][4] = {};
    mma_block<L_ST, 4, 4>(Qh, Ql, Kh, wm, wn, lane, acc);

    const float scale = 0.125f;
#pragma unroll
    for (int mt = 0; mt < 2; mt++) {
#pragma unroll
        for (int half = 0; half < 2; half++) {
            int rl = 32 * wm + 16 * mt + (lane >> 2) + 8 * half;
            int qi = qt + rl;
            const float* mrow = mask + (size_t)qi * SEQ;
            float* arow = attn + ((size_t)bh * SEQ + qi) * SEQ;
            float vv[4][2];
            float m = -1e30f;
#pragma unroll
            for (int nt = 0; nt < 4; nt++) {
                int kj = kt + 32 * wn + 8 * nt + 2 * (lane & 3);
                float2 mv = *(const float2*)(mrow + kj);
                float vx = acc[mt][nt][2 * half + 0] * scale + mv.x * (-1e9f);
                float vy = acc[mt][nt][2 * half + 1] * scale + mv.y * (-1e9f);
                *(float2*)(arow + kj) = make_float2(vx, vy);
                vv[nt][0] = vx; vv[nt][1] = vy;
                m = fmaxf(m, fmaxf(vx, vy));
            }
            m = fmaxf(m, __shfl_xor_sync(0xffffffffu, m, 1));
            m = fmaxf(m, __shfl_xor_sync(0xffffffffu, m, 2));
            float s = 0.f;
#pragma unroll
            for (int nt = 0; nt < 4; nt++)
                s += __expf(vv[nt][0] - m) + __expf(vv[nt][1] - m);
            s += __shfl_xor_sync(0xffffffffu, s, 1);
            s += __shfl_xor_sync(0xffffffffu, s, 2);
            if ((lane & 3) == 0) sstat[rl][wn] = make_float2(m, s);
        }
    }
    __syncthreads();

    if (tid < 128) {
        float2 a = sstat[tid][0], b = sstat[tid][1];
        float m = fmaxf(a.x, b.x);
        float s = a.y * __expf(a.x - m) + b.y * __expf(b.x - m);
        g_ps[((size_t)bh * SEQ + qt + tid) * 32 + blockIdx.x] = make_float2(m, s);
    }
}

// ============================ ctx: normalize + write attn + P @ V ============================
// 64(M=s_q) x 64(N=dh) per block, 128 threads, BK=32, 64 chunks, stride 80B.
#define C_ST 80
#define C_ARR 5120            // 64 x 80
#define C_BUF (3 * C_ARR)     // Ah, Al, Bh
__global__ void __launch_bounds__(128, 6)
ctx_mma(float* __restrict__ attn) {
    extern __shared__ char sm[];
    __shared__ float rowC[64];
    const int tid = threadIdx.x, lane = tid & 31, wid = tid >> 5;
    const int wm = wid >> 1, wn = wid & 1;
    const int bh = blockIdx.y;
    const int b = bh >> 4, h = bh & 15;
    const int mt0 = blockIdx.x * 64;
    float* A = attn + (size_t)bh * SEQ * SEQ + (size_t)mt0 * SEQ;
    const __half* Bv = g_vT + (size_t)bh * DH * SEQ;

    // combine 32 partial stats per row: C = m_row + ln(Z_row)
    if (tid < 64) {
        const float2* ps = &g_ps[((size_t)bh * SEQ + mt0 + tid) * 32];
        float m = -1e30f;
#pragma unroll
        for (int t = 0; t < 32; t++) m = fmaxf(m, ps[t].x);
        float z = 0.f;
#pragma unroll
        for (int t = 0; t < 32; t++) z += ps[t].y * __expf(ps[t].x - m);
        rowC[tid] = m + __logf(z);
    }
    __syncthreads();

    float Cw[4];
#pragma unroll
    for (int it = 0; it < 4; it++) Cw[it] = rowC[(it * 128 + tid) >> 3];

    float acc[2][4][4] = {};
    float4 ra[4];
    uint4  rb[2];

    auto loadA = [&](int k0) {
#pragma unroll
        for (int it = 0; it < 4; it++) {
            int idx = it * 128 + tid;
            int row = idx >> 3, c4 = idx & 7;    // 64 rows x 8 float4
            ra[it] = *(const float4*)(A + (size_t)row * SEQ + k0 + c4 * 4);
        }
    };
    auto loadB = [&](int k0) {
#pragma unroll
        for (int it = 0; it < 2; it++) {
            int idx = it * 128 + tid;
            int row = idx >> 2, c4 = idx & 3;    // 64 rows x 4 uint4
            rb[it] = *(const uint4*)(Bv + (size_t)row * SEQ + k0 + c4 * 8);
        }
    };
    auto store = [&](int buf, int k0) {
        char* Ah = sm + buf * C_BUF;
        char* Al = Ah + C_ARR;
        char* Bh = Al + C_ARR;
#pragma unroll
        for (int it = 0; it < 4; it++) {
            int idx = it * 128 + tid;
            int row = idx >> 3, c4 = idx & 7;
            float4 p;
            p.x = __expf(ra[it].x - Cw[it]);
            p.y = __expf(ra[it].y - Cw[it]);
            p.z = __expf(ra[it].z - Cw[it]);
            p.w = __expf(ra[it].w - Cw[it]);
            *(float4*)(A + (size_t)row * SEQ + k0 + c4 * 4) = p;
            put_split4(Ah, Al, row * C_ST + c4 * 8, pack_split(p.x),
                       pack_split(p.y), pack_split(p.z), pack_split(p.w));
        }
#pragma unroll
        for (int it = 0; it < 2; it++) {
            int idx = it * 128 + tid;
            int row = idx >> 2, c4 = idx & 3;
            *(uint4*)(Bh + row * C_ST + c4 * 16) = rb[it];
        }
    };

    loadA(0); loadB(0); store(0, 0);
    __syncthreads();
    for (int c = 0; c < 64; c++) {
        if (c < 63) { loadA((c + 1) * 32); loadB((c + 1) * 32); }
        char* base = sm + (c & 1) * C_BUF;
        mma_block<C_ST, 2, 4>(base, base + C_ARR, base + 2 * C_ARR,
                              wm, wn, lane, acc);
        if (c < 63) store((c + 1) & 1, (c + 1) * 32);
        __syncthreads();
    }

    // epilogue: write ctx as split halfs for out_mma
#pragma unroll
    for (int mt = 0; mt < 2; mt++) {
#pragma unroll
        for (int nt = 0; nt < 4; nt++) {
            int nl = 32 * wn + 8 * nt + 2 * (lane & 3);
            int m0 = mt0 + 32 * wm + 16 * mt + (lane >> 2);
#pragma unroll
            for (int half = 0; half < 2; half++) {
                int s = m0 + 8 * half;
                float va = acc[mt][nt][2 * half + 0];
                float vb = acc[mt][nt][2 * half + 1];
                __half ha = __float2half(va);
                __half hb = __float2half(vb);
                __half la = __float2half(va - __half2float(ha));
                __half lb = __float2half(vb - __half2float(hb));
                size_t off = ((size_t)b * SEQ + s) * DIM + h * DH + nl;
                *(__half2*)(g_ch + off) = __halves2half2(ha, hb);
                *(__half2*)(g_cl + off) = __halves2half2(la, lb);
            }
        }
    }
}

// ============================ launcher ============================
extern "C" void kernel_launch(void* const* d_in, const int* in_sizes, int n_in,
                              void* d_out, int out_size) {
    const float* x    = (const float*)d_in[0];
    const float* mask = (const float*)d_in[1];
    const float* Wq   = (const float*)d_in[2];
    const float* bq   = (const float*)d_in[3];
    const float* Wk   = (const float*)d_in[4];
    const float* bk   = (const float*)d_in[5];
    const float* Wv   = (const float*)d_in[6];
    const float* bv   = (const float*)d_in[7];
    const float* Wo   = (const float*)d_in[8];
    const float* bo   = (const float*)d_in[9];

    float* out  = (float*)d_out;                 // [B,S,D]
    float* attn = out + (size_t)BS * DIM;        // [B,H,S,S]

    const int projSmem = 2 * P_BUF;              // 60 KB
    const int logSmem  = 2 * L_QARR + L_KARR;    // 45 KB
    const int ctxSmem  = 2 * C_BUF;              // 30 KB
    cudaFuncSetAttribute(proj_mma,   cudaFuncAttributeMaxDynamicSharedMemorySize, projSmem);
    cudaFuncSetAttribute(logits_mma, cudaFuncAttributeMaxDynamicSharedMemorySize, logSmem);
    cudaFuncSetAttribute(ctx_mma,    cudaFuncAttributeMaxDynamicSharedMemorySize, ctxSmem);
    cudaFuncSetAttribute(out_mma,    cudaFuncAttributeMaxDynamicSharedMemorySize, projSmem);

    split_x<<<BS * DIM / 1024, 256>>>(x);
    transpose_pack_w<<<dim3(32, 32, 4), dim3(32, 8)>>>(Wq, Wk, Wv, Wo);
    proj_mma<<<dim3(8, 32, 3), 256, projSmem>>>(bq, bk, bv);
    transpose_v<<<dim3(64, 2, 32), dim3(32, 8)>>>();
    logits_mma<<<dim3(32, 16, 32), 256, logSmem>>>(mask, attn);
    ctx_mma<<<dim3(32, 32), 128, ctxSmem>>>(attn);
    out_mma<<<dim3(8, 32), 256, projSmem>>>(bo, out);
}

// round 10
// speedup vs baseline: 5.6159x; 1.1398x over previous
#include <cuda_runtime.h>
#include <cuda_fp16.h>
#include <stdint.h>

#define BB 2
#define SEQ 2048
#define DIM 1024
#define NH 16
#define DH 64
#define NBH (BB * NH)     // 32
#define BS  (BB * SEQ)    // 4096

// ---- fp16 scratch ----
__device__ __half g_xh[(size_t)BS * DIM];           // x hi
__device__ __half g_xl[(size_t)BS * DIM];           // x lo
__device__ __half g_wt[(size_t)4 * DIM * DIM];      // W^T fp16-hi: [z][n][k]
__device__ __half g_qh[(size_t)NBH * SEQ * DH];     // Q hi [bh][s][dh]
__device__ __half g_ql[(size_t)NBH * SEQ * DH];     // Q lo
__device__ __half g_kh[(size_t)NBH * SEQ * DH];     // K hi
__device__ __half g_vn[(size_t)NBH * SEQ * DH];     // V hi [bh][s][dh]
__device__ __half g_vT[(size_t)NBH * DH * SEQ];     // V^T hi [bh][dh][s]
__device__ __half g_ch[(size_t)BS * DIM];           // ctx hi [B*S][D]
__device__ __half g_cl[(size_t)BS * DIM];           // ctx lo
__device__ __half g_pt[(size_t)NBH * SEQ * SEQ];    // P~ = exp(x - m_tile), fp16
__device__ float2 g_ps[(size_t)NBH * SEQ * 32];     // per-64-tile stats (m, s)

// ============================ low-level helpers ============================
__device__ __forceinline__ uint32_t sptr(const void* p) {
    return (uint32_t)__cvta_generic_to_shared(p);
}

__device__ __forceinline__ void cp16(uint32_t dst, const void* src) {
    asm volatile("cp.async.cg.shared.global [%0], [%1], 16;" :: "r"(dst), "l"(src));
}
__device__ __forceinline__ void cp_commit() { asm volatile("cp.async.commit_group;"); }
__device__ __forceinline__ void cp_wait1()  { asm volatile("cp.async.wait_group 1;"); }
__device__ __forceinline__ void cp_wait0()  { asm volatile("cp.async.wait_group 0;"); }

__device__ __forceinline__ void ldm_x4(uint32_t* r, uint32_t addr) {
    asm volatile("ldmatrix.sync.aligned.m8n8.x4.shared.b16 {%0,%1,%2,%3}, [%4];"
                 : "=r"(r[0]), "=r"(r[1]), "=r"(r[2]), "=r"(r[3]) : "r"(addr));
}

__device__ __forceinline__ void mma16816(float* d, const uint32_t* a,
                                         const uint32_t* b) {
    asm volatile(
        "mma.sync.aligned.m16n8k16.row.col.f32.f16.f16.f32 "
        "{%0,%1,%2,%3}, {%4,%5,%6,%7}, {%8,%9}, {%0,%1,%2,%3};"
        : "+f"(d[0]), "+f"(d[1]), "+f"(d[2]), "+f"(d[3])
        : "r"(a[0]), "r"(a[1]), "r"(a[2]), "r"(a[3]), "r"(b[0]), "r"(b[1]));
}

__device__ __forceinline__ uint32_t pack_split(float x) {
    __half h = __float2half(x);
    float hf = __half2float(h);
    __half l = __float2half(x - hf);
    return (uint32_t)__half_as_ushort(h) | ((uint32_t)__half_as_ushort(l) << 16);
}

// ============================ warp-MMA blocks ============================
// 2-term: A hi+lo, B hi. acc += ah*bh + al*bh.
template <int STRIDE, int KSTEPS, int NT>
__device__ __forceinline__ void mma_block(const char* Ah, const char* Al,
                                          const char* Bh,
                                          int wm, int wn, int lane,
                                          float (&acc)[2][NT][4]) {
    uint32_t ahb = sptr(Ah), alb = sptr(Al), bhb = sptr(Bh);
#pragma unroll
    for (int ks = 0; ks < KSTEPS; ks++) {
        uint32_t ah[2][4], al[2][4];
#pragma unroll
        for (int mt = 0; mt < 2; mt++) {
            uint32_t off = (uint32_t)(32 * wm + 16 * mt + (lane & 15)) * STRIDE +
                           ((lane >> 4) * 16) + ks * 32;
            ldm_x4(ah[mt], ahb + off);
            ldm_x4(al[mt], alb + off);
        }
#pragma unroll
        for (int np = 0; np < NT / 2; np++) {
            uint32_t boff = (uint32_t)(NT * 8 * wn + np * 16 +
                                       ((lane >> 4) << 3) + (lane & 7)) * STRIDE +
                            (((lane >> 3) & 1) * 16) + ks * 32;
            uint32_t bh[4];
            ldm_x4(bh, bhb + boff);
#pragma unroll
            for (int mt = 0; mt < 2; mt++) {
                mma16816(acc[mt][2 * np],     ah[mt], bh);
                mma16816(acc[mt][2 * np],     al[mt], bh);
                mma16816(acc[mt][2 * np + 1], ah[mt], bh + 2);
                mma16816(acc[mt][2 * np + 1], al[mt], bh + 2);
            }
        }
    }
}

// 1-term: A hi only.
template <int STRIDE, int KSTEPS, int NT>
__device__ __forceinline__ void mma_block1(const char* Ah, const char* Bh,
                                           int wm, int wn, int lane,
                                           float (&acc)[2][NT][4]) {
    uint32_t ahb = sptr(Ah), bhb = sptr(Bh);
#pragma unroll
    for (int ks = 0; ks < KSTEPS; ks++) {
        uint32_t ah[2][4];
#pragma unroll
        for (int mt = 0; mt < 2; mt++) {
            uint32_t off = (uint32_t)(32 * wm + 16 * mt + (lane & 15)) * STRIDE +
                           ((lane >> 4) * 16) + ks * 32;
            ldm_x4(ah[mt], ahb + off);
        }
#pragma unroll
        for (int np = 0; np < NT / 2; np++) {
            uint32_t boff = (uint32_t)(NT * 8 * wn + np * 16 +
                                       ((lane >> 4) << 3) + (lane & 7)) * STRIDE +
                            (((lane >> 3) & 1) * 16) + ks * 32;
            uint32_t bh[4];
            ldm_x4(bh, bhb + boff);
#pragma unroll
            for (int mt = 0; mt < 2; mt++) {
                mma16816(acc[mt][2 * np],     ah[mt], bh);
                mma16816(acc[mt][2 * np + 1], ah[mt], bh + 2);
            }
        }
    }
}

// ============================ prep kernels ============================
__global__ void split_x(const float* __restrict__ x) {
    size_t i = ((size_t)blockIdx.x * blockDim.x + threadIdx.x) * 4;
    float4 f = *(const float4*)(x + i);
    uint32_t p0 = pack_split(f.x), p1 = pack_split(f.y);
    uint32_t p2 = pack_split(f.z), p3 = pack_split(f.w);
    uint2 h, l;
    h.x = (p0 & 0xffffu) | (p1 << 16);
    h.y = (p2 & 0xffffu) | (p3 << 16);
    l.x = (p0 >> 16) | (p1 & 0xffff0000u);
    l.y = (p2 >> 16) | (p3 & 0xffff0000u);
    *(uint2*)(g_xh + i) = h;
    *(uint2*)(g_xl + i) = l;
}

__global__ void transpose_pack_w(const float* __restrict__ Wq,
                                 const float* __restrict__ Wk,
                                 const float* __restrict__ Wv,
                                 const float* __restrict__ Wo) {
    __shared__ __half t[32][33];
    int z = blockIdx.z;
    const float* W = (z == 0) ? Wq : (z == 1) ? Wk : (z == 2) ? Wv : Wo;
    __half* dst = g_wt + (size_t)z * DIM * DIM;
    int n0 = blockIdx.x * 32, k0 = blockIdx.y * 32;
    int tx = threadIdx.x, ty = threadIdx.y;    // 32 x 8
#pragma unroll
    for (int r = 0; r < 4; r++) {
        int k = k0 + ty + r * 8;
        t[ty + r * 8][tx] = __float2half(W[(size_t)k * DIM + n0 + tx]);
    }
    __syncthreads();
#pragma unroll
    for (int r = 0; r < 4; r++) {
        int n = n0 + ty + r * 8;
        dst[(size_t)n * DIM + k0 + tx] = t[tx][ty + r * 8];
    }
}

__global__ void transpose_v() {
    __shared__ __half t[32][33];
    int bh = blockIdx.z;
    int s0 = blockIdx.x * 32, d0 = blockIdx.y * 32;
    int tx = threadIdx.x, ty = threadIdx.y;    // 32 x 8
    const __half* src = g_vn + (size_t)bh * SEQ * DH;
    __half* dst = g_vT + (size_t)bh * DH * SEQ;
#pragma unroll
    for (int r = 0; r < 4; r++) {
        int s = s0 + ty + r * 8;
        t[ty + r * 8][tx] = src[(size_t)s * DH + d0 + tx];
    }
    __syncthreads();
#pragma unroll
    for (int r = 0; r < 4; r++) {
        int d = d0 + ty + r * 8;
        dst[(size_t)d * SEQ + s0 + tx] = t[tx][ty + r * 8];
    }
}

// ============================ GEMM body (proj & out): cp.async 3-stage ============================
#define P_ST 80
#define P_ARR 10240
#define P_BUF (3 * P_ARR)

template <typename EPI>
__device__ __forceinline__ void gemm128_body(const __half* Xh, const __half* Xl,
                                             const __half* Bt, char* sm, EPI epi) {
    const int tid = threadIdx.x, lane = tid & 31, wid = tid >> 5;
    const int wm = wid >> 1, wn = wid & 1;
    float acc[2][8][4] = {};

    const int r0 = tid >> 2, c0 = (tid & 3) * 16;             // smem byte col
    const int r1 = (tid + 256) >> 2, c1 = ((tid + 256) & 3) * 16;

    auto issue = [&](int c) {
        char* base = sm + (c % 3) * P_BUF;
        uint32_t Ah = sptr(base), Al = Ah + P_ARR, Bh = Al + P_ARR;
        int k0 = c * 32;
        cp16(Ah + r0 * P_ST + c0, Xh + (size_t)r0 * DIM + k0 + c0 / 2);
        cp16(Ah + r1 * P_ST + c1, Xh + (size_t)r1 * DIM + k0 + c1 / 2);
        cp16(Al + r0 * P_ST + c0, Xl + (size_t)r0 * DIM + k0 + c0 / 2);
        cp16(Al + r1 * P_ST + c1, Xl + (size_t)r1 * DIM + k0 + c1 / 2);
        cp16(Bh + r0 * P_ST + c0, Bt + (size_t)r0 * DIM + k0 + c0 / 2);
        cp16(Bh + r1 * P_ST + c1, Bt + (size_t)r1 * DIM + k0 + c1 / 2);
        cp_commit();
    };
    issue(0); issue(1);
    for (int c = 0; c < 32; c++) {
        if (c < 31) cp_wait1(); else cp_wait0();
        __syncthreads();
        char* base = sm + (c % 3) * P_BUF;
        mma_block<P_ST, 2, 8>(base, base + P_ARR, base + 2 * P_ARR,
                              wm, wn, lane, acc);
        if (c + 2 < 32) issue(c + 2);
    }
    epi(acc, wm, wn, lane);
}

__global__ void __launch_bounds__(256, 2)
proj_mma(const float* __restrict__ bq, const float* __restrict__ bk,
         const float* __restrict__ bv) {
    extern __shared__ char sm[];
    const int z = blockIdx.z;
    const int bn = blockIdx.x * 128, bm = blockIdx.y * 128;
    const __half* Bt = g_wt + (size_t)z * DIM * DIM + (size_t)bn * DIM;
    const float* bias = (z == 0) ? bq : (z == 1) ? bk : bv;

    gemm128_body(g_xh + (size_t)bm * DIM, g_xl + (size_t)bm * DIM, Bt, sm,
        [&](float (&acc)[2][8][4], int wm, int wn, int lane) {
#pragma unroll
            for (int mt = 0; mt < 2; mt++) {
#pragma unroll
                for (int nt = 0; nt < 8; nt++) {
                    int n = bn + 64 * wn + 8 * nt + 2 * (lane & 3);
                    float bx = bias[n], by = bias[n + 1];
                    int h = n >> 6, dh = n & 63;
                    int m0 = bm + 32 * wm + 16 * mt + (lane >> 2);
#pragma unroll
                    for (int half = 0; half < 2; half++) {
                        int m = m0 + 8 * half;
                        int b = m >> 11, s = m & 2047;
                        float va = acc[mt][nt][2 * half + 0] + bx;
                        float vb = acc[mt][nt][2 * half + 1] + by;
                        size_t off = ((size_t)(b * NH + h) * SEQ + s) * DH + dh;
                        __half ha = __float2half(va);
                        __half hb = __float2half(vb);
                        if (z == 0) {
                            __half la = __float2half(va - __half2float(ha));
                            __half lb = __float2half(vb - __half2float(hb));
                            *(__half2*)(g_qh + off) = __halves2half2(ha, hb);
                            *(__half2*)(g_ql + off) = __halves2half2(la, lb);
                        } else if (z == 1) {
                            *(__half2*)(g_kh + off) = __halves2half2(ha, hb);
                        } else {
                            *(__half2*)(g_vn + off) = __halves2half2(ha, hb);
                        }
                    }
                }
            }
        });
}

__global__ void __launch_bounds__(256, 2)
out_mma(const float* __restrict__ bo, float* __restrict__ out) {
    extern __shared__ char sm[];
    const int bn = blockIdx.x * 128, bm = blockIdx.y * 128;
    const __half* Bt = g_wt + (size_t)3 * DIM * DIM + (size_t)bn * DIM;

    gemm128_body(g_ch + (size_t)bm * DIM, g_cl + (size_t)bm * DIM, Bt, sm,
        [&](float (&acc)[2][8][4], int wm, int wn, int lane) {
#pragma unroll
            for (int mt = 0; mt < 2; mt++) {
#pragma unroll
                for (int nt = 0; nt < 8; nt++) {
                    int n = bn + 64 * wn + 8 * nt + 2 * (lane & 3);
                    float bx = bo[n], by = bo[n + 1];
                    int m0 = bm + 32 * wm + 16 * mt + (lane >> 2);
#pragma unroll
                    for (int half = 0; half < 2; half++) {
                        int m = m0 + 8 * half;
                        float2 o;
                        o.x = acc[mt][nt][2 * half + 0] + bx;
                        o.y = acc[mt][nt][2 * half + 1] + by;
                        *(float2*)(out + (size_t)m * DIM + n) = o;
                    }
                }
            }
        });
}

// ============================ logits: P~ fp16 + tile stats ============================
// 128q x 64k per block, K=64 one-shot. stride 144B.
#define L_ST 144
#define L_QARR 18432          // 128 x 144
#define L_KARR 9216           // 64 x 144
__global__ void __launch_bounds__(256, 3)
logits_mma(const float* __restrict__ mask) {
    extern __shared__ char sm[];
    __shared__ float sm_m[128][2], sm_s[128][2];
    const int tid = threadIdx.x, lane = tid & 31, wid = tid >> 5;
    const int wm = wid >> 1, wn = wid & 1;
    const int bh = blockIdx.z;
    const int qt = blockIdx.y * 128, kt = blockIdx.x * 64;

    // one-shot cp.async staging (Q split, K hi)
    {
        uint32_t Qh = sptr(sm), Ql = Qh + L_QARR, Kh = Ql + L_QARR;
#pragma unroll
        for (int it = 0; it < 4; it++) {
            int idx = it * 256 + tid;
            int row = idx >> 3, c = idx & 7;
            size_t src = ((size_t)bh * SEQ + qt + row) * DH + c * 8;
            cp16(Qh + row * L_ST + c * 16, g_qh + src);
            cp16(Ql + row * L_ST + c * 16, g_ql + src);
        }
#pragma unroll
        for (int it = 0; it < 2; it++) {
            int idx = it * 256 + tid;
            int row = idx >> 3, c = idx & 7;
            cp16(Kh + row * L_ST + c * 16,
                 g_kh + ((size_t)bh * SEQ + kt + row) * DH + c * 8);
        }
        cp_commit(); cp_wait0();
    }
    __syncthreads();

    float acc[2][4][4] = {};
    mma_block<L_ST, 4, 4>(sm, sm + L_QARR, sm + 2 * L_QARR, wm, wn, lane, acc);

    const float scale = 0.125f;
    // phase 1: v = acc*scale + mask*(-1e9) in place; local max per (row, wn-32)
#pragma unroll
    for (int mt = 0; mt < 2; mt++) {
#pragma unroll
        for (int half = 0; half < 2; half++) {
            int rl = 32 * wm + 16 * mt + (lane >> 2) + 8 * half;
            int qi = qt + rl;
            const float* mrow = mask + (size_t)qi * SEQ;
            float m = -1e30f;
#pragma unroll
            for (int nt = 0; nt < 4; nt++) {
                int kj = kt + 32 * wn + 8 * nt + 2 * (lane & 3);
                float2 mv = *(const float2*)(mrow + kj);
                float vx = acc[mt][nt][2 * half + 0] * scale + mv.x * (-1e9f);
                float vy = acc[mt][nt][2 * half + 1] * scale + mv.y * (-1e9f);
                acc[mt][nt][2 * half + 0] = vx;
                acc[mt][nt][2 * half + 1] = vy;
                m = fmaxf(m, fmaxf(vx, vy));
            }
            m = fmaxf(m, __shfl_xor_sync(0xffffffffu, m, 1));
            m = fmaxf(m, __shfl_xor_sync(0xffffffffu, m, 2));
            if ((lane & 3) == 0) sm_m[rl][wn] = m;
        }
    }
    __syncthreads();

    // phase 2: unified tile max, exp, store P~ fp16, local sums
#pragma unroll
    for (int mt = 0; mt < 2; mt++) {
#pragma unroll
        for (int half = 0; half < 2; half++) {
            int rl = 32 * wm + 16 * mt + (lane >> 2) + 8 * half;
            int qi = qt + rl;
            float mT = fmaxf(sm_m[rl][0], sm_m[rl][1]);
            __half* prow = g_pt + ((size_t)bh * SEQ + qi) * SEQ;
            float s = 0.f;
#pragma unroll
            for (int nt = 0; nt < 4; nt++) {
                int kj = kt + 32 * wn + 8 * nt + 2 * (lane & 3);
                float px = __expf(acc[mt][nt][2 * half + 0] - mT);
                float py = __expf(acc[mt][nt][2 * half + 1] - mT);
                s += px + py;
                *(__half2*)(prow + kj) = __floats2half2_rn(px, py);
            }
            s += __shfl_xor_sync(0xffffffffu, s, 1);
            s += __shfl_xor_sync(0xffffffffu, s, 2);
            if ((lane & 3) == 0) sm_s[rl][wn] = s;
        }
    }
    __syncthreads();

    // phase 3: per-row tile stats
    if (tid < 128) {
        float m = fmaxf(sm_m[tid][0], sm_m[tid][1]);
        float s = sm_s[tid][0] + sm_s[tid][1];
        g_ps[((size_t)bh * SEQ + qt + tid) * 32 + blockIdx.x] = make_float2(m, s);
    }
}

// ============================ ctx: scale + write attn + P @ V (1-term) ============================
// 64(M=s_q) x 64(N=dh) per block, 128 threads, BK=32, 64 chunks, stride 80B.
#define C_ST 80
#define C_ARR 5120            // 64 x 80
#define C_BUF (2 * C_ARR)     // Ah, Bh
__global__ void __launch_bounds__(128, 6)
ctx_mma(float* __restrict__ attn) {
    extern __shared__ char sm[];
    __shared__ float sc_tab[64][32];
    const int tid = threadIdx.x, lane = tid & 31, wid = tid >> 5;
    const int wm = wid >> 1, wn = wid & 1;
    const int bh = blockIdx.y;
    const int b = bh >> 4, h = bh & 15;
    const int mt0 = blockIdx.x * 64;
    const __half* Pt = g_pt + ((size_t)bh * SEQ + mt0) * SEQ;
    float* Aout = attn + ((size_t)bh * SEQ + mt0) * SEQ;
    const __half* Bv = g_vT + (size_t)bh * DH * SEQ;

    // per-row: C = m + ln Z over 32 tiles; sc[row][t] = exp(m_t - C)
    if (tid < 64) {
        const float2* ps = &g_ps[((size_t)bh * SEQ + mt0 + tid) * 32];
        float m = -1e30f;
#pragma unroll
        for (int t = 0; t < 32; t++) m = fmaxf(m, ps[t].x);
        float z = 0.f;
#pragma unroll
        for (int t = 0; t < 32; t++) z += ps[t].y * __expf(ps[t].x - m);
        float C = m + __logf(z);
#pragma unroll
        for (int t = 0; t < 32; t++) sc_tab[tid][t] = __expf(ps[t].x - C);
    }
    __syncthreads();

    float acc[2][4][4] = {};
    uint4 rpa[2], rvb[2];

    auto loadA = [&](int k0) {
#pragma unroll
        for (int it = 0; it < 2; it++) {
            int idx = it * 128 + tid;
            int row = idx >> 2, c4 = idx & 3;     // 64 rows x 4 uint4
            rpa[it] = *(const uint4*)(Pt + (size_t)row * SEQ + k0 + c4 * 8);
        }
    };
    auto loadB = [&](int k0) {
#pragma unroll
        for (int it = 0; it < 2; it++) {
            int idx = it * 128 + tid;
            int row = idx >> 2, c4 = idx & 3;
            rvb[it] = *(const uint4*)(Bv + (size_t)row * SEQ + k0 + c4 * 8);
        }
    };
    auto store = [&](int buf, int k0) {
        char* Ah = sm + buf * C_BUF;
        char* Bh = Ah + C_ARR;
        int t = k0 >> 6;
#pragma unroll
        for (int it = 0; it < 2; it++) {
            int idx = it * 128 + tid;
            int row = idx >> 2, c4 = idx & 3;
            float s = sc_tab[row][t];
            const __half2* hp = (const __half2*)&rpa[it];
            float2 f0 = __half22float2(hp[0]);
            float2 f1 = __half22float2(hp[1]);
            float2 f2 = __half22float2(hp[2]);
            float2 f3 = __half22float2(hp[3]);
            f0.x *= s; f0.y *= s; f1.x *= s; f1.y *= s;
            f2.x *= s; f2.y *= s; f3.x *= s; f3.y *= s;
            float* arow = Aout + (size_t)row * SEQ + k0 + c4 * 8;
            *(float4*)(arow)     = make_float4(f0.x, f0.y, f1.x, f1.y);
            *(float4*)(arow + 4) = make_float4(f2.x, f2.y, f3.x, f3.y);
            uint4 o;
            ((__half2*)&o)[0] = __floats2half2_rn(f0.x, f0.y);
            ((__half2*)&o)[1] = __floats2half2_rn(f1.x, f1.y);
            ((__half2*)&o)[2] = __floats2half2_rn(f2.x, f2.y);
            ((__half2*)&o)[3] = __floats2half2_rn(f3.x, f3.y);
            *(uint4*)(Ah + row * C_ST + c4 * 16) = o;
        }
#pragma unroll
        for (int it = 0; it < 2; it++) {
            int idx = it * 128 + tid;
            int row = idx >> 2, c4 = idx & 3;
            *(uint4*)(Bh + row * C_ST + c4 * 16) = rvb[it];
        }
    };

    loadA(0); loadB(0); store(0, 0);
    __syncthreads();
    for (int c = 0; c < 64; c++) {
        if (c < 63) { loadA((c + 1) * 32); loadB((c + 1) * 32); }
        char* base = sm + (c & 1) * C_BUF;
        mma_block1<C_ST, 2, 4>(base, base + C_ARR, wm, wn, lane, acc);
        if (c < 63) store((c + 1) & 1, (c + 1) * 32);
        __syncthreads();
    }

    // epilogue: ctx as split halfs for out_mma
#pragma unroll
    for (int mt = 0; mt < 2; mt++) {
#pragma unroll
        for (int nt = 0; nt < 4; nt++) {
            int nl = 32 * wn + 8 * nt + 2 * (lane & 3);
            int m0 = mt0 + 32 * wm + 16 * mt + (lane >> 2);
#pragma unroll
            for (int half = 0; half < 2; half++) {
                int s = m0 + 8 * half;
                float va = acc[mt][nt][2 * half + 0];
                float vb = acc[mt][nt][2 * half + 1];
                __half ha = __float2half(va);
                __half hb = __float2half(vb);
                __half la = __float2half(va - __half2float(ha));
                __half lb = __float2half(vb - __half2float(hb));
                size_t off = ((size_t)b * SEQ + s) * DIM + h * DH + nl;
                *(__half2*)(g_ch + off) = __halves2half2(ha, hb);
                *(__half2*)(g_cl + off) = __halves2half2(la, lb);
            }
        }
    }
}

// ============================ launcher ============================
extern "C" void kernel_launch(void* const* d_in, const int* in_sizes, int n_in,
                              void* d_out, int out_size) {
    const float* x    = (const float*)d_in[0];
    const float* mask = (const float*)d_in[1];
    const float* Wq   = (const float*)d_in[2];
    const float* bq   = (const float*)d_in[3];
    const float* Wk   = (const float*)d_in[4];
    const float* bk   = (const float*)d_in[5];
    const float* Wv   = (const float*)d_in[6];
    const float* bv   = (const float*)d_in[7];
    const float* Wo   = (const float*)d_in[8];
    const float* bo   = (const float*)d_in[9];

    float* out  = (float*)d_out;                 // [B,S,D]
    float* attn = out + (size_t)BS * DIM;        // [B,H,S,S]

    const int projSmem = 3 * P_BUF;              // 92160
    const int logSmem  = 2 * L_QARR + L_KARR;    // 46080
    const int ctxSmem  = 2 * C_BUF;              // 20480
    cudaFuncSetAttribute(proj_mma,   cudaFuncAttributeMaxDynamicSharedMemorySize, projSmem);
    cudaFuncSetAttribute(logits_mma, cudaFuncAttributeMaxDynamicSharedMemorySize, logSmem);
    cudaFuncSetAttribute(ctx_mma,    cudaFuncAttributeMaxDynamicSharedMemorySize, ctxSmem);
    cudaFuncSetAttribute(out_mma,    cudaFuncAttributeMaxDynamicSharedMemorySize, projSmem);

    split_x<<<BS * DIM / 1024, 256>>>(x);
    transpose_pack_w<<<dim3(32, 32, 4), dim3(32, 8)>>>(Wq, Wk, Wv, Wo);
    proj_mma<<<dim3(8, 32, 3), 256, projSmem>>>(bq, bk, bv);
    transpose_v<<<dim3(64, 2, 32), dim3(32, 8)>>>();
    logits_mma<<<dim3(32, 16, 32), 256, logSmem>>>(mask);
    ctx_mma<<<dim3(32, 32), 128, ctxSmem>>>(attn);
    out_mma<<<dim3(8, 32), 256, projSmem>>>(bo, out);
}